// round 1
// baseline (speedup 1.0000x reference)
#include <cuda_runtime.h>
#include <math.h>

#define TOK   4096      // 2 * 2048 tokens
#define SEQ   2048
#define DIMM  1024
#define HEADS 16
#define HD    64
#define MLPD  4096
#define DEPTH 6
#define ATT_SCALE 0.03125f   // 1024^-0.5

// ---------------- scratch (device globals; no allocation allowed) ----------------
__device__ float g_ln  [TOK * DIMM];        // 16 MB
__device__ float g_qkv [TOK * 3 * DIMM];    // 48 MB
__device__ float g_attn[TOK * DIMM];        // 16 MB
__device__ float g_mlp [TOK * MLPD];        // 64 MB

// ---------------- copy x -> h ----------------
__global__ void copy_kernel(const float4* __restrict__ src, float4* __restrict__ dst, int n)
{
    int i = blockIdx.x * blockDim.x + threadIdx.x;
    if (i < n) dst[i] = src[i];
}

// ---------------- layernorm: y = (x-m)*rsqrt(v+eps)*g + b  (one block per token) ----------------
__global__ __launch_bounds__(256) void ln_kernel(const float* __restrict__ x,
                                                 const float* __restrict__ g,
                                                 const float* __restrict__ b,
                                                 float* __restrict__ y)
{
    int t = blockIdx.x, tid = threadIdx.x;
    const float4* xv = (const float4*)(x + (size_t)t * DIMM);
    float4 v = xv[tid];
    float s  = v.x + v.y + v.z + v.w;
    float s2 = v.x*v.x + v.y*v.y + v.z*v.z + v.w*v.w;
    #pragma unroll
    for (int o = 16; o > 0; o >>= 1) {
        s  += __shfl_xor_sync(0xffffffffu, s,  o);
        s2 += __shfl_xor_sync(0xffffffffu, s2, o);
    }
    __shared__ float rs[8], rs2[8];
    int w = tid >> 5, lane = tid & 31;
    if (lane == 0) { rs[w] = s; rs2[w] = s2; }
    __syncthreads();
    if (tid == 0) {
        float a = 0.f, a2 = 0.f;
        #pragma unroll
        for (int i = 0; i < 8; i++) { a += rs[i]; a2 += rs2[i]; }
        rs[0] = a; rs2[0] = a2;
    }
    __syncthreads();
    float mean = rs[0] * (1.f / DIMM);
    float var  = rs2[0] * (1.f / DIMM) - mean * mean;
    float inv  = rsqrtf(var + 1e-5f);
    float4 gv = ((const float4*)g)[tid];
    float4 bv = ((const float4*)b)[tid];
    float4 o;
    o.x = (v.x - mean) * inv * gv.x + bv.x;
    o.y = (v.y - mean) * inv * gv.y + bv.y;
    o.z = (v.z - mean) * inv * gv.z + bv.z;
    o.w = (v.w - mean) * inv * gv.w + bv.w;
    ((float4*)(y + (size_t)t * DIMM))[tid] = o;
}

// ---------------- sgemm: C(MxN) = A(MxK) @ B(KxN) [+ bias] [+ gelu | += C] ----------------
// EPI: 0 = store, 1 = bias + exact gelu, 2 = C += AB + bias (residual)
template<int EPI>
__global__ __launch_bounds__(256) void sgemm(int M, int N, int K,
                                             const float* __restrict__ A,
                                             const float* __restrict__ B,
                                             const float* __restrict__ bias,
                                             float* __restrict__ C)
{
    const int BM = 128, BN = 128, BK = 8, TM = 8, TN = 8;
    __shared__ float As[BK][BM];
    __shared__ float Bs[BK][BN];

    int bx = blockIdx.x, by = blockIdx.y;
    int tid = threadIdx.x;
    int tx = tid & 15, ty = tid >> 4;

    const float* Ap = A + (size_t)by * BM * K;
    const float* Bp = B + (size_t)bx * BN;
    float*       Cp = C + (size_t)by * BM * N + (size_t)bx * BN;

    int arow = tid >> 1, acol = (tid & 1) * 4;
    int brow = tid >> 5, bcol = (tid & 31) * 4;

    float acc[TM][TN];
    #pragma unroll
    for (int i = 0; i < TM; i++)
        #pragma unroll
        for (int j = 0; j < TN; j++) acc[i][j] = 0.f;

    for (int k0 = 0; k0 < K; k0 += BK) {
        float4 av = *(const float4*)(Ap + (size_t)arow * K + k0 + acol);
        As[acol + 0][arow] = av.x;
        As[acol + 1][arow] = av.y;
        As[acol + 2][arow] = av.z;
        As[acol + 3][arow] = av.w;
        float4 bv = *(const float4*)(Bp + (size_t)(k0 + brow) * N + bcol);
        *(float4*)(&Bs[brow][bcol]) = bv;
        __syncthreads();
        #pragma unroll
        for (int k = 0; k < BK; k++) {
            float ar[TM], br[TN];
            *(float4*)(ar)     = *(const float4*)(&As[k][ty * TM]);
            *(float4*)(ar + 4) = *(const float4*)(&As[k][ty * TM + 4]);
            *(float4*)(br)     = *(const float4*)(&Bs[k][tx * TN]);
            *(float4*)(br + 4) = *(const float4*)(&Bs[k][tx * TN + 4]);
            #pragma unroll
            for (int i = 0; i < TM; i++)
                #pragma unroll
                for (int j = 0; j < TN; j++)
                    acc[i][j] += ar[i] * br[j];
        }
        __syncthreads();
    }

    const float* bp = (EPI == 0) ? (const float*)0 : (bias + (size_t)bx * BN);
    #pragma unroll
    for (int i = 0; i < TM; i++) {
        int row = ty * TM + i;
        #pragma unroll
        for (int j = 0; j < TN; j += 4) {
            float* cptr = Cp + (size_t)row * N + tx * TN + j;
            float4 r;
            if (EPI == 0) {
                r = make_float4(acc[i][j], acc[i][j+1], acc[i][j+2], acc[i][j+3]);
            } else if (EPI == 1) {
                float v[4];
                #pragma unroll
                for (int c = 0; c < 4; c++) {
                    float t = acc[i][j + c] + bp[tx * TN + j + c];
                    v[c] = 0.5f * t * (1.f + erff(t * 0.70710678118654752f));
                }
                r = make_float4(v[0], v[1], v[2], v[3]);
            } else {
                float4 cold = *(const float4*)cptr;
                r.x = cold.x + acc[i][j + 0] + bp[tx * TN + j + 0];
                r.y = cold.y + acc[i][j + 1] + bp[tx * TN + j + 1];
                r.z = cold.z + acc[i][j + 2] + bp[tx * TN + j + 2];
                r.w = cold.w + acc[i][j + 3] + bp[tx * TN + j + 3];
            }
            *(float4*)cptr = r;
        }
    }
}

// ---------------- flash attention (fp32): BQ=128 queries/block, BK=64 keys/tile ----------------
// grid = (16 qblocks, 16 heads, 2 batch), 256 threads.
// smem: q_t[64][128] (transposed), k_t[64][64] (transposed), v_s[64][64], s_t[64][128] (key-major), stats
#define ATTN_SMEM ((64*128 + 64*64 + 64*64 + 64*128 + 3*128) * 4)

__global__ __launch_bounds__(256) void attn_kernel(const float* __restrict__ qkv,
                                                   float* __restrict__ out)
{
    extern __shared__ float sm[];
    float* q_t = sm;               // [d][r]  64x128
    float* k_t = q_t + 64 * 128;   // [d][j]  64x64
    float* v_s = k_t + 64 * 64;    // [j][d]  64x64
    float* s_t = v_s + 64 * 64;    // [j][r]  64x128
    float* m_s = s_t + 64 * 128;   // [128]
    float* l_s = m_s + 128;
    float* c_s = l_s + 128;

    const int tid = threadIdx.x;
    const int qb = blockIdx.x, head = blockIdx.y, batch = blockIdx.z;
    const size_t tok0 = (size_t)batch * SEQ;
    const float* base = qkv + tok0 * (3 * DIMM) + head * HD;

    // load Q tile transposed
    {
        int r  = tid >> 1;
        int h4 = tid & 1;
        const float* qrow = base + (size_t)(qb * 128 + r) * (3 * DIMM);
        #pragma unroll
        for (int i = 0; i < 8; i++) {
            int d4 = h4 + 2 * i;
            float4 v = *(const float4*)(qrow + d4 * 4);
            q_t[(d4 * 4 + 0) * 128 + r] = v.x;
            q_t[(d4 * 4 + 1) * 128 + r] = v.y;
            q_t[(d4 * 4 + 2) * 128 + r] = v.z;
            q_t[(d4 * 4 + 3) * 128 + r] = v.w;
        }
    }
    if (tid < 128) { m_s[tid] = -INFINITY; l_s[tid] = 0.f; }

    const int tr = tid & 31;   // row group: rows tr*4 .. tr*4+3
    const int tc = tid >> 5;   // col group: cols tc*8 .. tc*8+7
    float O[4][8];
    #pragma unroll
    for (int i = 0; i < 4; i++)
        #pragma unroll
        for (int j = 0; j < 8; j++) O[i][j] = 0.f;

    for (int kt = 0; kt < SEQ / 64; kt++) {
        __syncthreads();   // prev-iter consumers of k_t/v_s/s_t done; Q load done (iter 0)
        // load K tile transposed
        {
            int j  = tid >> 2;
            int h4 = tid & 3;
            const float* krow = base + (size_t)(kt * 64 + j) * (3 * DIMM) + DIMM;
            #pragma unroll
            for (int i = 0; i < 4; i++) {
                int d4 = h4 + 4 * i;
                float4 v = *(const float4*)(krow + d4 * 4);
                k_t[(d4 * 4 + 0) * 64 + j] = v.x;
                k_t[(d4 * 4 + 1) * 64 + j] = v.y;
                k_t[(d4 * 4 + 2) * 64 + j] = v.z;
                k_t[(d4 * 4 + 3) * 64 + j] = v.w;
            }
            // V tile row-major
            #pragma unroll
            for (int i = 0; i < 4; i++) {
                int f  = tid + 256 * i;
                int vj = f >> 4;
                int d4 = f & 15;
                const float* vrow = base + (size_t)(kt * 64 + vj) * (3 * DIMM) + 2 * DIMM;
                *(float4*)(v_s + vj * 64 + d4 * 4) = *(const float4*)(vrow + d4 * 4);
            }
        }
        __syncthreads();

        // S = scale * Q K^T  (4x8 micro-tile)
        float sf[4][8];
        #pragma unroll
        for (int i = 0; i < 4; i++)
            #pragma unroll
            for (int j = 0; j < 8; j++) sf[i][j] = 0.f;
        #pragma unroll 8
        for (int d = 0; d < 64; d++) {
            float4 a  = *(const float4*)(q_t + d * 128 + tr * 4);
            float4 b0 = *(const float4*)(k_t + d * 64 + tc * 8);
            float4 b1 = *(const float4*)(k_t + d * 64 + tc * 8 + 4);
            float av[4] = {a.x, a.y, a.z, a.w};
            float bv[8] = {b0.x, b0.y, b0.z, b0.w, b1.x, b1.y, b1.z, b1.w};
            #pragma unroll
            for (int i = 0; i < 4; i++)
                #pragma unroll
                for (int j = 0; j < 8; j++)
                    sf[i][j] += av[i] * bv[j];
        }
        #pragma unroll
        for (int j = 0; j < 8; j++) {
            float4 v = make_float4(sf[0][j] * ATT_SCALE, sf[1][j] * ATT_SCALE,
                                   sf[2][j] * ATT_SCALE, sf[3][j] * ATT_SCALE);
            *(float4*)(s_t + (tc * 8 + j) * 128 + tr * 4) = v;
        }
        __syncthreads();

        // online softmax row update (rows 0..127 by thread id)
        if (tid < 128) {
            float m_old = m_s[tid];
            float mx = m_old;
            #pragma unroll 8
            for (int j = 0; j < 64; j++) mx = fmaxf(mx, s_t[j * 128 + tid]);
            float corr = __expf(m_old - mx);
            float l = l_s[tid] * corr;
            #pragma unroll 8
            for (int j = 0; j < 64; j++) {
                float p = __expf(s_t[j * 128 + tid] - mx);
                s_t[j * 128 + tid] = p;
                l += p;
            }
            m_s[tid] = mx; l_s[tid] = l; c_s[tid] = corr;
        }
        __syncthreads();

        // rescale accumulators, then O += P V
        float cf[4];
        #pragma unroll
        for (int i = 0; i < 4; i++) cf[i] = c_s[tr * 4 + i];
        #pragma unroll
        for (int i = 0; i < 4; i++)
            #pragma unroll
            for (int j = 0; j < 8; j++) O[i][j] *= cf[i];
        #pragma unroll 8
        for (int j2 = 0; j2 < 64; j2++) {
            float4 p  = *(const float4*)(s_t + j2 * 128 + tr * 4);
            float4 b0 = *(const float4*)(v_s + j2 * 64 + tc * 8);
            float4 b1 = *(const float4*)(v_s + j2 * 64 + tc * 8 + 4);
            float pv[4] = {p.x, p.y, p.z, p.w};
            float bv[8] = {b0.x, b0.y, b0.z, b0.w, b1.x, b1.y, b1.z, b1.w};
            #pragma unroll
            for (int i = 0; i < 4; i++)
                #pragma unroll
                for (int j = 0; j < 8; j++)
                    O[i][j] += pv[i] * bv[j];
        }
    }

    // normalize and write out[token][head*64 + c]
    float inv[4];
    #pragma unroll
    for (int i = 0; i < 4; i++) inv[i] = 1.f / l_s[tr * 4 + i];
    #pragma unroll
    for (int i = 0; i < 4; i++) {
        size_t row = tok0 + (size_t)qb * 128 + tr * 4 + i;
        float* op = out + row * DIMM + head * HD + tc * 8;
        float4 r0 = make_float4(O[i][0] * inv[i], O[i][1] * inv[i], O[i][2] * inv[i], O[i][3] * inv[i]);
        float4 r1 = make_float4(O[i][4] * inv[i], O[i][5] * inv[i], O[i][6] * inv[i], O[i][7] * inv[i]);
        *(float4*)op       = r0;
        *(float4*)(op + 4) = r1;
    }
}

// ---------------- driver ----------------
extern "C" void kernel_launch(void* const* d_in, const int* in_sizes, int n_in,
                              void* d_out, int out_size)
{
    const float* x    = (const float*)d_in[0];
    const float* Wqkv = (const float*)d_in[1];
    const float* Wout = (const float*)d_in[2];
    const float* bout = (const float*)d_in[3];
    const float* ln1g = (const float*)d_in[4];
    const float* ln1b = (const float*)d_in[5];
    const float* ln2g = (const float*)d_in[6];
    const float* ln2b = (const float*)d_in[7];
    const float* W1   = (const float*)d_in[8];
    const float* b1   = (const float*)d_in[9];
    const float* W2   = (const float*)d_in[10];
    const float* b2   = (const float*)d_in[11];
    float* h = (float*)d_out;   // residual stream lives in the output buffer

    float *ln, *qkv, *att, *mlp;
    cudaGetSymbolAddress((void**)&ln,  g_ln);
    cudaGetSymbolAddress((void**)&qkv, g_qkv);
    cudaGetSymbolAddress((void**)&att, g_attn);
    cudaGetSymbolAddress((void**)&mlp, g_mlp);

    cudaFuncSetAttribute(attn_kernel, cudaFuncAttributeMaxDynamicSharedMemorySize, ATTN_SMEM);

    // h = x
    copy_kernel<<<TOK, 256>>>((const float4*)x, (float4*)h, TOK * DIMM / 4);

    for (int l = 0; l < DEPTH; l++) {
        // attention block
        ln_kernel<<<TOK, 256>>>(h, ln1g + (size_t)l * DIMM, ln1b + (size_t)l * DIMM, ln);
        sgemm<0><<<dim3(3 * DIMM / 128, TOK / 128), 256>>>(TOK, 3 * DIMM, DIMM,
                ln, Wqkv + (size_t)l * DIMM * 3 * DIMM, (const float*)0, qkv);
        attn_kernel<<<dim3(SEQ / 128, HEADS, 2), 256, ATTN_SMEM>>>(qkv, att);
        sgemm<2><<<dim3(DIMM / 128, TOK / 128), 256>>>(TOK, DIMM, DIMM,
                att, Wout + (size_t)l * DIMM * DIMM, bout + (size_t)l * DIMM, h);
        // ffn block
        ln_kernel<<<TOK, 256>>>(h, ln2g + (size_t)l * DIMM, ln2b + (size_t)l * DIMM, ln);
        sgemm<1><<<dim3(MLPD / 128, TOK / 128), 256>>>(TOK, MLPD, DIMM,
                ln, W1 + (size_t)l * DIMM * MLPD, b1 + (size_t)l * MLPD, mlp);
        sgemm<2><<<dim3(DIMM / 128, TOK / 128), 256>>>(TOK, DIMM, MLPD,
                mlp, W2 + (size_t)l * MLPD * DIMM, b2 + (size_t)l * DIMM, h);
    }
}

// round 3
// speedup vs baseline: 1.5347x; 1.5347x over previous
#include <cuda_runtime.h>
#include <cuda_bf16.h>
#include <math.h>
#include <stdint.h>

#define TOK   4096
#define SEQ   2048
#define DIMM  1024
#define HEADS 16
#define HD    64
#define MLPD  4096
#define DEPTH 6
#define ATT_SCALE 0.03125f

// ---------------- scratch ----------------
__device__ float         g_qkv[TOK * 3 * DIMM];                 // 48MB fp32
__device__ __nv_bfloat16 g_ah[TOK * DIMM], g_al[TOK * DIMM];    // act hi/lo
__device__ __nv_bfloat16 g_mh[TOK * MLPD], g_ml[TOK * MLPD];    // mlp hidden hi/lo
__device__ __nv_bfloat16 g_wh[DIMM * MLPD], g_wl[DIMM * MLPD];  // transposed weight hi/lo

// ---------------- PTX helpers (baseline PTX only: sm_80-era) ----------------
__device__ __forceinline__ uint32_t smem_u32(const void* p) {
    uint32_t a;
    asm("{ .reg .u64 t; cvta.to.shared.u64 t, %1; cvt.u32.u64 %0, t; }" : "=r"(a) : "l"(p));
    return a;
}
__device__ __forceinline__ void cp16(uint32_t dst, const void* src) {
    asm volatile("cp.async.cg.shared.global [%0], [%1], 16;" :: "r"(dst), "l"(src));
}
#define CP_COMMIT()  asm volatile("cp.async.commit_group;")
#define CP_WAIT(n)   asm volatile("cp.async.wait_group " #n ";")

__device__ __forceinline__ void ldsm4(uint32_t* r, uint32_t addr) {
    asm volatile("ldmatrix.sync.aligned.m8n8.x4.shared.b16 {%0,%1,%2,%3}, [%4];"
        : "=r"(r[0]), "=r"(r[1]), "=r"(r[2]), "=r"(r[3]) : "r"(addr));
}
__device__ __forceinline__ void mma16816(float* c, const uint32_t* a, uint32_t b0, uint32_t b1) {
    asm volatile(
        "mma.sync.aligned.m16n8k16.row.col.f32.bf16.bf16.f32 "
        "{%0,%1,%2,%3}, {%4,%5,%6,%7}, {%8,%9}, {%0,%1,%2,%3};"
        : "+f"(c[0]), "+f"(c[1]), "+f"(c[2]), "+f"(c[3])
        : "r"(a[0]), "r"(a[1]), "r"(a[2]), "r"(a[3]), "r"(b0), "r"(b1));
}

// ---------------- copy ----------------
__global__ void copy_kernel(const float4* __restrict__ src, float4* __restrict__ dst, int n) {
    int i = blockIdx.x * blockDim.x + threadIdx.x;
    if (i < n) dst[i] = src[i];
}

// ---------------- weight convert + transpose: W[K,N] fp32 -> Wt[N,K] bf16 hi/lo ----------------
__global__ __launch_bounds__(1024) void wconv(const float* __restrict__ W, int K, int N,
                                              __nv_bfloat16* __restrict__ Th,
                                              __nv_bfloat16* __restrict__ Tl) {
    __shared__ float t[32][33];
    int tx = threadIdx.x, ty = threadIdx.y;
    int n0 = blockIdx.x * 32, k0 = blockIdx.y * 32;
    t[ty][tx] = W[(size_t)(k0 + ty) * N + n0 + tx];
    __syncthreads();
    float v = t[tx][ty];
    __nv_bfloat16 hi = __float2bfloat16(v);
    size_t o = (size_t)(n0 + ty) * K + k0 + tx;
    Th[o] = hi;
    Tl[o] = __float2bfloat16(v - __bfloat162float(hi));
}

// ---------------- layernorm -> bf16 hi/lo ----------------
__global__ __launch_bounds__(256) void ln_kernel(const float* __restrict__ x,
                                                 const float* __restrict__ g,
                                                 const float* __restrict__ b,
                                                 __nv_bfloat16* __restrict__ yh,
                                                 __nv_bfloat16* __restrict__ yl) {
    int t = blockIdx.x, tid = threadIdx.x;
    const float4* xv = (const float4*)(x + (size_t)t * DIMM);
    float4 v = xv[tid];
    float s  = v.x + v.y + v.z + v.w;
    float s2 = v.x * v.x + v.y * v.y + v.z * v.z + v.w * v.w;
    #pragma unroll
    for (int o = 16; o > 0; o >>= 1) {
        s  += __shfl_xor_sync(0xffffffffu, s,  o);
        s2 += __shfl_xor_sync(0xffffffffu, s2, o);
    }
    __shared__ float rs[8], rs2[8];
    int w = tid >> 5, lane = tid & 31;
    if (lane == 0) { rs[w] = s; rs2[w] = s2; }
    __syncthreads();
    if (tid == 0) {
        float a = 0.f, a2 = 0.f;
        #pragma unroll
        for (int i = 0; i < 8; i++) { a += rs[i]; a2 += rs2[i]; }
        rs[0] = a; rs2[0] = a2;
    }
    __syncthreads();
    float mean = rs[0] * (1.f / DIMM);
    float var  = rs2[0] * (1.f / DIMM) - mean * mean;
    float inv  = rsqrtf(var + 1e-5f);
    float4 gv = ((const float4*)g)[tid];
    float4 bv = ((const float4*)b)[tid];
    float o0 = (v.x - mean) * inv * gv.x + bv.x;
    float o1 = (v.y - mean) * inv * gv.y + bv.y;
    float o2 = (v.z - mean) * inv * gv.z + bv.z;
    float o3 = (v.w - mean) * inv * gv.w + bv.w;
    __nv_bfloat16 h0 = __float2bfloat16(o0), h1 = __float2bfloat16(o1);
    __nv_bfloat16 h2 = __float2bfloat16(o2), h3 = __float2bfloat16(o3);
    __nv_bfloat16 hv[4] = {h0, h1, h2, h3};
    __nv_bfloat16 lv[4] = {
        __float2bfloat16(o0 - __bfloat162float(h0)), __float2bfloat16(o1 - __bfloat162float(h1)),
        __float2bfloat16(o2 - __bfloat162float(h2)), __float2bfloat16(o3 - __bfloat162float(h3))};
    *(uint2*)(yh + (size_t)t * DIMM + tid * 4) = *(uint2*)hv;
    *(uint2*)(yl + (size_t)t * DIMM + tid * 4) = *(uint2*)lv;
}

// ---------------- HMMA GEMM: C[M,N] = A @ B^T (B stored [N,K]) ----------------
// bf16 3-split (AhBh + AhBl + AlBh), fp32 accum in registers.
// 128x128 CTA tile, BK=32, 8 warps (2M x 4N), warp tile 64x32, mma.m16n8k16.
// EPI: 0 = store fp32; 1 = bias + exact gelu -> bf16 hi/lo; 2 = C += AB + bias
#define BKG  32
#define PADR 40   // smem row stride in bf16 elems (80 B) -> conflict-free ldmatrix

template<int EPI>
__global__ __launch_bounds__(256, 2) void gemm_mma(
    const __nv_bfloat16* __restrict__ Ah, const __nv_bfloat16* __restrict__ Al,
    const __nv_bfloat16* __restrict__ Bh, const __nv_bfloat16* __restrict__ Bl,
    const float* __restrict__ bias, float* __restrict__ C,
    __nv_bfloat16* __restrict__ Oh, __nv_bfloat16* __restrict__ Ol,
    int M, int N, int K)
{
    __shared__ __align__(16) __nv_bfloat16 As[2][128 * PADR];
    __shared__ __align__(16) __nv_bfloat16 Bs[2][128 * PADR];

    const int tid = threadIdx.x;
    const int wid = tid >> 5, lane = tid & 31;
    const int wm = wid >> 2, wn = wid & 3;          // 2 x 4 warp grid
    const int bn = blockIdx.x, bm = blockIdx.y;

    const __nv_bfloat16* Aps[3] = {Ah + (size_t)bm * 128 * K, Ah + (size_t)bm * 128 * K, Al + (size_t)bm * 128 * K};
    const __nv_bfloat16* Bps[3] = {Bh + (size_t)bn * 128 * K, Bl + (size_t)bn * 128 * K, Bh + (size_t)bn * 128 * K};

    const int KC  = K / BKG;         // chunks per pass
    const int NC3 = 3 * KC;

    const uint32_t asm_base = smem_u32(As);
    const uint32_t bsm_base = smem_u32(Bs);
    const int row_ld = tid >> 2, c16 = tid & 3;     // 256 threads -> rows 0..63 here; two iters cover 128

    float acc[4][4][4];
    #pragma unroll
    for (int i = 0; i < 4; i++)
        #pragma unroll
        for (int j = 0; j < 4; j++)
            #pragma unroll
            for (int c = 0; c < 4; c++) acc[i][j][c] = 0.f;

    // ---- chunk loader ----
    auto load_chunk = [&](int ci, int st) {
        int p  = ci / KC;
        int kc = ci - p * KC;
        const __nv_bfloat16* a = Aps[p] + kc * BKG;
        const __nv_bfloat16* b = Bps[p] + kc * BKG;
        uint32_t ad = asm_base + st * (128 * PADR * 2);
        uint32_t bd = bsm_base + st * (128 * PADR * 2);
        #pragma unroll
        for (int i = 0; i < 2; i++) {
            int r = row_ld + 64 * i;
            cp16(ad + r * (PADR * 2) + c16 * 16, a + (size_t)r * K + c16 * 8);
            cp16(bd + r * (PADR * 2) + c16 * 16, b + (size_t)r * K + c16 * 8);
        }
        CP_COMMIT();
    };

    load_chunk(0, 0);

    for (int ci = 0; ci < NC3; ci++) {
        int st = ci & 1;
        if (ci + 1 < NC3) { load_chunk(ci + 1, st ^ 1); CP_WAIT(1); }
        else              { CP_WAIT(0); }
        __syncthreads();

        uint32_t abase = asm_base + st * (128 * PADR * 2);
        uint32_t bbase = bsm_base + st * (128 * PADR * 2);
        #pragma unroll
        for (int ks = 0; ks < 2; ks++) {
            int k0 = ks * 16;
            uint32_t a_frag[4][4];
            uint32_t b_frag[4][2];
            // A: 4 m16 tiles
            #pragma unroll
            for (int mt = 0; mt < 4; mt++) {
                int row = wm * 64 + mt * 16 + (lane & 15);
                int col = k0 + (lane >> 4) * 8;
                ldsm4(a_frag[mt], abase + row * (PADR * 2) + col * 2);
            }
            // B: 2 ldsm4, each covers two n8 tiles
            #pragma unroll
            for (int bt = 0; bt < 2; bt++) {
                uint32_t r[4];
                int row = wn * 32 + bt * 16 + (lane & 15);
                int col = k0 + (lane >> 4) * 8;
                ldsm4(r, bbase + row * (PADR * 2) + col * 2);
                b_frag[bt * 2 + 0][0] = r[0]; b_frag[bt * 2 + 0][1] = r[2];
                b_frag[bt * 2 + 1][0] = r[1]; b_frag[bt * 2 + 1][1] = r[3];
            }
            #pragma unroll
            for (int mt = 0; mt < 4; mt++)
                #pragma unroll
                for (int nt = 0; nt < 4; nt++)
                    mma16816(acc[mt][nt], a_frag[mt], b_frag[nt][0], b_frag[nt][1]);
        }
        __syncthreads();
    }

    // ---- epilogue ----
    const int rgrp = lane >> 2;            // 0..7
    const int cgrp = (lane & 3) * 2;       // 0,2,4,6
    const float* bp = (EPI != 0) ? (bias + (size_t)bn * 128) : (const float*)0;
    #pragma unroll
    for (int mt = 0; mt < 4; mt++) {
        #pragma unroll
        for (int half = 0; half < 2; half++) {
            size_t grow = (size_t)bm * 128 + wm * 64 + mt * 16 + rgrp + half * 8;
            #pragma unroll
            for (int nt = 0; nt < 4; nt++) {
                int lcol = wn * 32 + nt * 8 + cgrp;
                size_t gcol = (size_t)bn * 128 + lcol;
                float v0 = acc[mt][nt][half * 2 + 0];
                float v1 = acc[mt][nt][half * 2 + 1];
                if (EPI == 0) {
                    *(float2*)(C + grow * N + gcol) = make_float2(v0, v1);
                } else if (EPI == 1) {
                    float t0 = v0 + bp[lcol],   t1 = v1 + bp[lcol + 1];
                    float g0 = 0.5f * t0 * (1.f + erff(t0 * 0.70710678118654752f));
                    float g1 = 0.5f * t1 * (1.f + erff(t1 * 0.70710678118654752f));
                    __nv_bfloat16 h0 = __float2bfloat16(g0), h1 = __float2bfloat16(g1);
                    __nv_bfloat16 hv[2] = {h0, h1};
                    __nv_bfloat16 lv[2] = {__float2bfloat16(g0 - __bfloat162float(h0)),
                                           __float2bfloat16(g1 - __bfloat162float(h1))};
                    *(uint32_t*)(Oh + grow * N + gcol) = *(uint32_t*)hv;
                    *(uint32_t*)(Ol + grow * N + gcol) = *(uint32_t*)lv;
                } else {
                    float2 old = *(float2*)(C + grow * N + gcol);
                    *(float2*)(C + grow * N + gcol) =
                        make_float2(old.x + v0 + bp[lcol], old.y + v1 + bp[lcol + 1]);
                }
            }
        }
    }
}

// ---------------- flash attention fp32 (bf16 hi/lo epilogue) ----------------
#define ATTN_SMEM ((64 * 128 + 64 * 64 + 64 * 64 + 64 * 128 + 3 * 128) * 4)

__global__ __launch_bounds__(256) void attn_kernel(const float* __restrict__ qkv,
                                                   __nv_bfloat16* __restrict__ out_hi,
                                                   __nv_bfloat16* __restrict__ out_lo)
{
    extern __shared__ float smf[];
    float* q_t = smf;
    float* k_t = q_t + 64 * 128;
    float* v_s = k_t + 64 * 64;
    float* s_t = v_s + 64 * 64;
    float* m_s = s_t + 64 * 128;
    float* l_s = m_s + 128;
    float* c_s = l_s + 128;

    const int tid = threadIdx.x;
    const int qb = blockIdx.x, head = blockIdx.y, batch = blockIdx.z;
    const size_t tok0 = (size_t)batch * SEQ;
    const float* base = qkv + tok0 * (3 * DIMM) + head * HD;

    {
        int r = tid >> 1, h4 = tid & 1;
        const float* qrow = base + (size_t)(qb * 128 + r) * (3 * DIMM);
        #pragma unroll
        for (int i = 0; i < 8; i++) {
            int d4 = h4 + 2 * i;
            float4 v = *(const float4*)(qrow + d4 * 4);
            q_t[(d4 * 4 + 0) * 128 + r] = v.x;
            q_t[(d4 * 4 + 1) * 128 + r] = v.y;
            q_t[(d4 * 4 + 2) * 128 + r] = v.z;
            q_t[(d4 * 4 + 3) * 128 + r] = v.w;
        }
    }
    if (tid < 128) { m_s[tid] = -INFINITY; l_s[tid] = 0.f; }

    const int tr = tid & 31;
    const int tc = tid >> 5;
    float O[4][8];
    #pragma unroll
    for (int i = 0; i < 4; i++)
        #pragma unroll
        for (int j = 0; j < 8; j++) O[i][j] = 0.f;

    for (int kt = 0; kt < SEQ / 64; kt++) {
        __syncthreads();
        {
            int j = tid >> 2, h4 = tid & 3;
            const float* krow = base + (size_t)(kt * 64 + j) * (3 * DIMM) + DIMM;
            #pragma unroll
            for (int i = 0; i < 4; i++) {
                int d4 = h4 + 4 * i;
                float4 v = *(const float4*)(krow + d4 * 4);
                k_t[(d4 * 4 + 0) * 64 + j] = v.x;
                k_t[(d4 * 4 + 1) * 64 + j] = v.y;
                k_t[(d4 * 4 + 2) * 64 + j] = v.z;
                k_t[(d4 * 4 + 3) * 64 + j] = v.w;
            }
            #pragma unroll
            for (int i = 0; i < 4; i++) {
                int f = tid + 256 * i;
                int vj = f >> 4, d4 = f & 15;
                const float* vrow = base + (size_t)(kt * 64 + vj) * (3 * DIMM) + 2 * DIMM;
                *(float4*)(v_s + vj * 64 + d4 * 4) = *(const float4*)(vrow + d4 * 4);
            }
        }
        __syncthreads();

        float sf[4][8];
        #pragma unroll
        for (int i = 0; i < 4; i++)
            #pragma unroll
            for (int j = 0; j < 8; j++) sf[i][j] = 0.f;
        #pragma unroll 8
        for (int d = 0; d < 64; d++) {
            float4 a  = *(const float4*)(q_t + d * 128 + tr * 4);
            float4 b0 = *(const float4*)(k_t + d * 64 + tc * 8);
            float4 b1 = *(const float4*)(k_t + d * 64 + tc * 8 + 4);
            float av[4] = {a.x, a.y, a.z, a.w};
            float bv[8] = {b0.x, b0.y, b0.z, b0.w, b1.x, b1.y, b1.z, b1.w};
            #pragma unroll
            for (int i = 0; i < 4; i++)
                #pragma unroll
                for (int j = 0; j < 8; j++) sf[i][j] += av[i] * bv[j];
        }
        #pragma unroll
        for (int j = 0; j < 8; j++) {
            float4 v = make_float4(sf[0][j] * ATT_SCALE, sf[1][j] * ATT_SCALE,
                                   sf[2][j] * ATT_SCALE, sf[3][j] * ATT_SCALE);
            *(float4*)(s_t + (tc * 8 + j) * 128 + tr * 4) = v;
        }
        __syncthreads();

        if (tid < 128) {
            float m_old = m_s[tid];
            float mx = m_old;
            #pragma unroll 8
            for (int j = 0; j < 64; j++) mx = fmaxf(mx, s_t[j * 128 + tid]);
            float corr = __expf(m_old - mx);
            float l = l_s[tid] * corr;
            #pragma unroll 8
            for (int j = 0; j < 64; j++) {
                float p = __expf(s_t[j * 128 + tid] - mx);
                s_t[j * 128 + tid] = p;
                l += p;
            }
            m_s[tid] = mx; l_s[tid] = l; c_s[tid] = corr;
        }
        __syncthreads();

        float cf[4];
        #pragma unroll
        for (int i = 0; i < 4; i++) cf[i] = c_s[tr * 4 + i];
        #pragma unroll
        for (int i = 0; i < 4; i++)
            #pragma unroll
            for (int j = 0; j < 8; j++) O[i][j] *= cf[i];
        #pragma unroll 8
        for (int j2 = 0; j2 < 64; j2++) {
            float4 p  = *(const float4*)(s_t + j2 * 128 + tr * 4);
            float4 b0 = *(const float4*)(v_s + j2 * 64 + tc * 8);
            float4 b1 = *(const float4*)(v_s + j2 * 64 + tc * 8 + 4);
            float pv[4] = {p.x, p.y, p.z, p.w};
            float bv[8] = {b0.x, b0.y, b0.z, b0.w, b1.x, b1.y, b1.z, b1.w};
            #pragma unroll
            for (int i = 0; i < 4; i++)
                #pragma unroll
                for (int j = 0; j < 8; j++) O[i][j] += pv[i] * bv[j];
        }
    }

    float inv[4];
    #pragma unroll
    for (int i = 0; i < 4; i++) inv[i] = 1.f / l_s[tr * 4 + i];
    #pragma unroll
    for (int i = 0; i < 4; i++) {
        size_t row = tok0 + (size_t)qb * 128 + tr * 4 + i;
        size_t idx = row * DIMM + head * HD + tc * 8;
        __nv_bfloat16 hv[8], lv[8];
        #pragma unroll
        for (int j = 0; j < 8; j++) {
            float v = O[i][j] * inv[i];
            __nv_bfloat16 hi = __float2bfloat16(v);
            hv[j] = hi;
            lv[j] = __float2bfloat16(v - __bfloat162float(hi));
        }
        *(uint4*)(out_hi + idx) = *(uint4*)hv;
        *(uint4*)(out_lo + idx) = *(uint4*)lv;
    }
}

// ---------------- driver ----------------
extern "C" void kernel_launch(void* const* d_in, const int* in_sizes, int n_in,
                              void* d_out, int out_size)
{
    const float* x    = (const float*)d_in[0];
    const float* Wqkv = (const float*)d_in[1];
    const float* Wout = (const float*)d_in[2];
    const float* bout = (const float*)d_in[3];
    const float* ln1g = (const float*)d_in[4];
    const float* ln1b = (const float*)d_in[5];
    const float* ln2g = (const float*)d_in[6];
    const float* ln2b = (const float*)d_in[7];
    const float* W1   = (const float*)d_in[8];
    const float* b1   = (const float*)d_in[9];
    const float* W2   = (const float*)d_in[10];
    const float* b2   = (const float*)d_in[11];
    float* h = (float*)d_out;

    float* qkv; __nv_bfloat16 *ah, *al, *mh, *ml, *wh, *wl;
    cudaGetSymbolAddress((void**)&qkv, g_qkv);
    cudaGetSymbolAddress((void**)&ah,  g_ah);
    cudaGetSymbolAddress((void**)&al,  g_al);
    cudaGetSymbolAddress((void**)&mh,  g_mh);
    cudaGetSymbolAddress((void**)&ml,  g_ml);
    cudaGetSymbolAddress((void**)&wh,  g_wh);
    cudaGetSymbolAddress((void**)&wl,  g_wl);

    cudaFuncSetAttribute(attn_kernel, cudaFuncAttributeMaxDynamicSharedMemorySize, ATTN_SMEM);

    copy_kernel<<<TOK, 256>>>((const float4*)x, (float4*)h, TOK * DIMM / 4);

    for (int l = 0; l < DEPTH; l++) {
        // --- attention block ---
        wconv<<<dim3(3 * DIMM / 32, DIMM / 32), dim3(32, 32)>>>(
            Wqkv + (size_t)l * DIMM * 3 * DIMM, DIMM, 3 * DIMM, wh, wl);
        ln_kernel<<<TOK, 256>>>(h, ln1g + (size_t)l * DIMM, ln1b + (size_t)l * DIMM, ah, al);
        gemm_mma<0><<<dim3(3 * DIMM / 128, TOK / 128), 256>>>(
            ah, al, wh, wl, (const float*)0, qkv, (__nv_bfloat16*)0, (__nv_bfloat16*)0,
            TOK, 3 * DIMM, DIMM);
        attn_kernel<<<dim3(SEQ / 128, HEADS, 2), 256, ATTN_SMEM>>>(qkv, ah, al);
        wconv<<<dim3(DIMM / 32, DIMM / 32), dim3(32, 32)>>>(
            Wout + (size_t)l * DIMM * DIMM, DIMM, DIMM, wh, wl);
        gemm_mma<2><<<dim3(DIMM / 128, TOK / 128), 256>>>(
            ah, al, wh, wl, bout + (size_t)l * DIMM, h, (__nv_bfloat16*)0, (__nv_bfloat16*)0,
            TOK, DIMM, DIMM);
        // --- ffn block ---
        ln_kernel<<<TOK, 256>>>(h, ln2g + (size_t)l * DIMM, ln2b + (size_t)l * DIMM, ah, al);
        wconv<<<dim3(MLPD / 32, DIMM / 32), dim3(32, 32)>>>(
            W1 + (size_t)l * DIMM * MLPD, DIMM, MLPD, wh, wl);
        gemm_mma<1><<<dim3(MLPD / 128, TOK / 128), 256>>>(
            ah, al, wh, wl, b1 + (size_t)l * MLPD, (float*)0, mh, ml,
            TOK, MLPD, DIMM);
        wconv<<<dim3(DIMM / 32, MLPD / 32), dim3(32, 32)>>>(
            W2 + (size_t)l * MLPD * DIMM, MLPD, DIMM, wh, wl);
        gemm_mma<2><<<dim3(DIMM / 128, TOK / 128), 256>>>(
            mh, ml, wh, wl, b2 + (size_t)l * DIMM, h, (__nv_bfloat16*)0, (__nv_bfloat16*)0,
            TOK, DIMM, MLPD);
    }
}

// round 4
// speedup vs baseline: 2.2736x; 1.4815x over previous
#include <cuda_runtime.h>
#include <cuda_bf16.h>
#include <math.h>
#include <stdint.h>

#define TOK   4096
#define SEQ   2048
#define DIMM  1024
#define HEADS 16
#define HD    64
#define MLPD  4096
#define DEPTH 6
#define ATT_SCALE 0.03125f

// ---------------- scratch ----------------
__device__ __nv_bfloat16 g_ah[TOK * DIMM], g_al[TOK * DIMM];    // ln out / attn out hi-lo
__device__ __nv_bfloat16 g_mh[TOK * MLPD], g_ml[TOK * MLPD];    // mlp hidden hi-lo
__device__ __nv_bfloat16 g_wh[DIMM * MLPD], g_wl[DIMM * MLPD];  // transposed weight hi-lo
__device__ __nv_bfloat16 g_qh[TOK * DIMM], g_ql[TOK * DIMM];    // Q hi-lo [token][dim]
__device__ __nv_bfloat16 g_kh[TOK * DIMM], g_kl[TOK * DIMM];    // K hi-lo [token][dim]
__device__ __nv_bfloat16 g_vh[DIMM * TOK], g_vl[DIMM * TOK];    // V hi-lo transposed [dim][token]

// ---------------- PTX helpers ----------------
__device__ __forceinline__ uint32_t smem_u32(const void* p) {
    uint32_t a;
    asm("{ .reg .u64 t; cvta.to.shared.u64 t, %1; cvt.u32.u64 %0, t; }" : "=r"(a) : "l"(p));
    return a;
}
#define SWZ(o) ((o) ^ (((o) >> 3) & 0x70))
__device__ __forceinline__ void cp16(uint32_t dst, const void* src) {
    asm volatile("cp.async.cg.shared.global [%0], [%1], 16;" :: "r"(dst), "l"(src));
}
#define CP_COMMIT()  asm volatile("cp.async.commit_group;")
#define CP_WAIT(n)   asm volatile("cp.async.wait_group " #n ";")

__device__ __forceinline__ void ldsm4(uint32_t* r, uint32_t addr) {
    asm volatile("ldmatrix.sync.aligned.m8n8.x4.shared.b16 {%0,%1,%2,%3}, [%4];"
        : "=r"(r[0]), "=r"(r[1]), "=r"(r[2]), "=r"(r[3]) : "r"(addr));
}
__device__ __forceinline__ void mma16816(float* c, const uint32_t* a, uint32_t b0, uint32_t b1) {
    asm volatile(
        "mma.sync.aligned.m16n8k16.row.col.f32.bf16.bf16.f32 "
        "{%0,%1,%2,%3}, {%4,%5,%6,%7}, {%8,%9}, {%0,%1,%2,%3};"
        : "+f"(c[0]), "+f"(c[1]), "+f"(c[2]), "+f"(c[3])
        : "r"(a[0]), "r"(a[1]), "r"(a[2]), "r"(a[3]), "r"(b0), "r"(b1));
}
__device__ __forceinline__ uint32_t packh(float a, float b) {
    __nv_bfloat162 t = __floats2bfloat162_rn(a, b);
    return *(uint32_t*)&t;
}
__device__ __forceinline__ uint32_t packl(float a, float b) {
    float ah = __bfloat162float(__float2bfloat16(a));
    float bh = __bfloat162float(__float2bfloat16(b));
    return packh(a - ah, b - bh);
}

// ---------------- copy ----------------
__global__ void copy_kernel(const float4* __restrict__ src, float4* __restrict__ dst, int n) {
    int i = blockIdx.x * blockDim.x + threadIdx.x;
    if (i < n) dst[i] = src[i];
}

// ---------------- weight convert + transpose: W[K,N] fp32 -> Wt[N,K] bf16 hi/lo ----------------
__global__ __launch_bounds__(1024) void wconv(const float* __restrict__ W, int K, int N,
                                              __nv_bfloat16* __restrict__ Th,
                                              __nv_bfloat16* __restrict__ Tl) {
    __shared__ float t[32][33];
    int tx = threadIdx.x, ty = threadIdx.y;
    int n0 = blockIdx.x * 32, k0 = blockIdx.y * 32;
    t[ty][tx] = W[(size_t)(k0 + ty) * N + n0 + tx];
    __syncthreads();
    float v = t[tx][ty];
    __nv_bfloat16 hi = __float2bfloat16(v);
    size_t o = (size_t)(n0 + ty) * K + k0 + tx;
    Th[o] = hi;
    Tl[o] = __float2bfloat16(v - __bfloat162float(hi));
}

// ---------------- layernorm -> bf16 hi/lo ----------------
__global__ __launch_bounds__(256) void ln_kernel(const float* __restrict__ x,
                                                 const float* __restrict__ g,
                                                 const float* __restrict__ b,
                                                 __nv_bfloat16* __restrict__ yh,
                                                 __nv_bfloat16* __restrict__ yl) {
    int t = blockIdx.x, tid = threadIdx.x;
    const float4* xv = (const float4*)(x + (size_t)t * DIMM);
    float4 v = xv[tid];
    float s  = v.x + v.y + v.z + v.w;
    float s2 = v.x * v.x + v.y * v.y + v.z * v.z + v.w * v.w;
    #pragma unroll
    for (int o = 16; o > 0; o >>= 1) {
        s  += __shfl_xor_sync(0xffffffffu, s,  o);
        s2 += __shfl_xor_sync(0xffffffffu, s2, o);
    }
    __shared__ float rs[8], rs2[8];
    int w = tid >> 5, lane = tid & 31;
    if (lane == 0) { rs[w] = s; rs2[w] = s2; }
    __syncthreads();
    if (tid == 0) {
        float a = 0.f, a2 = 0.f;
        #pragma unroll
        for (int i = 0; i < 8; i++) { a += rs[i]; a2 += rs2[i]; }
        rs[0] = a; rs2[0] = a2;
    }
    __syncthreads();
    float mean = rs[0] * (1.f / DIMM);
    float var  = rs2[0] * (1.f / DIMM) - mean * mean;
    float inv  = rsqrtf(var + 1e-5f);
    float4 gv = ((const float4*)g)[tid];
    float4 bv = ((const float4*)b)[tid];
    float o0 = (v.x - mean) * inv * gv.x + bv.x;
    float o1 = (v.y - mean) * inv * gv.y + bv.y;
    float o2 = (v.z - mean) * inv * gv.z + bv.z;
    float o3 = (v.w - mean) * inv * gv.w + bv.w;
    __nv_bfloat16 h0 = __float2bfloat16(o0), h1 = __float2bfloat16(o1);
    __nv_bfloat16 h2 = __float2bfloat16(o2), h3 = __float2bfloat16(o3);
    __nv_bfloat16 hv[4] = {h0, h1, h2, h3};
    __nv_bfloat16 lv[4] = {
        __float2bfloat16(o0 - __bfloat162float(h0)), __float2bfloat16(o1 - __bfloat162float(h1)),
        __float2bfloat16(o2 - __bfloat162float(h2)), __float2bfloat16(o3 - __bfloat162float(h3))};
    *(uint2*)(yh + (size_t)t * DIMM + tid * 4) = *(uint2*)hv;
    *(uint2*)(yl + (size_t)t * DIMM + tid * 4) = *(uint2*)lv;
}

// ---------------- HMMA GEMM, merged 3-split per K-chunk ----------------
// C[M,N] = A @ B^T (B stored [N,K]); AhBh + AhBl + AlBh; fp32 accum.
// 128x128 CTA tile, BK=32 chunk carries all 4 operand tiles; 8 warps 2Mx4N, warp 64x32.
// EPI: 0 store fp32; 1 bias+gelu->bf16 hi/lo; 2 C += AB+bias; 3 qkv split write
#define PADR 40
#define PADT (128 * PADR)                 // elems per tile
#define GSTG (4 * PADT * 2)               // bytes per stage (40960)
#define GEMM_SMEM_B (2 * GSTG)            // 81920

template<int EPI>
__global__ __launch_bounds__(256, 2) void gemm_mma(
    const __nv_bfloat16* __restrict__ Ah, const __nv_bfloat16* __restrict__ Al,
    const __nv_bfloat16* __restrict__ Bh, const __nv_bfloat16* __restrict__ Bl,
    const float* __restrict__ bias, float* __restrict__ C,
    __nv_bfloat16* __restrict__ Oh, __nv_bfloat16* __restrict__ Ol,
    __nv_bfloat16* __restrict__ Qh, __nv_bfloat16* __restrict__ Ql,
    __nv_bfloat16* __restrict__ Kh, __nv_bfloat16* __restrict__ Kl,
    __nv_bfloat16* __restrict__ Vh, __nv_bfloat16* __restrict__ Vl,
    int M, int N, int K)
{
    extern __shared__ __align__(1024) char smg[];
    const uint32_t sb = smem_u32(smg);
    const int tid = threadIdx.x;
    const int wid = tid >> 5, lane = tid & 31;
    const int wm = wid >> 2, wn = wid & 3;
    const int bn = blockIdx.x, bm = blockIdx.y;

    const __nv_bfloat16* src4[4] = {
        Ah + (size_t)bm * 128 * K, Al + (size_t)bm * 128 * K,
        Bh + (size_t)bn * 128 * K, Bl + (size_t)bn * 128 * K};

    const int NC = K / 32;

    float acc[4][4][4];
    #pragma unroll
    for (int i = 0; i < 4; i++)
        #pragma unroll
        for (int j = 0; j < 4; j++)
            #pragma unroll
            for (int c = 0; c < 4; c++) acc[i][j][c] = 0.f;

    const int lr = tid >> 2, lc = tid & 3;
    auto load_chunk = [&](int kc, int st) {
        uint32_t u = sb + st * GSTG;
        #pragma unroll
        for (int t = 0; t < 4; t++) {
            const __nv_bfloat16* g = src4[t] + kc * 32;
            #pragma unroll
            for (int i = 0; i < 2; i++) {
                int r = lr + 64 * i;
                cp16(u + t * (PADT * 2) + r * (PADR * 2) + lc * 16, g + (size_t)r * K + lc * 8);
            }
        }
        CP_COMMIT();
    };

    load_chunk(0, 0);

    for (int k = 0; k < NC; k++) {
        int st = k & 1;
        if (k + 1 < NC) { load_chunk(k + 1, st ^ 1); CP_WAIT(1); }
        else            { CP_WAIT(0); }
        __syncthreads();

        uint32_t u = sb + st * GSTG;
        #pragma unroll
        for (int ks = 0; ks < 2; ks++) {
            int cb = ks * 32 + (lane >> 4) * 16;
            uint32_t bh_[4][2], bl_[4][2];
            #pragma unroll
            for (int bt = 0; bt < 2; bt++) {
                uint32_t t[4];
                uint32_t off = (wn * 32 + bt * 16 + (lane & 15)) * (PADR * 2) + cb;
                ldsm4(t, u + 2 * (PADT * 2) + off);
                bh_[bt * 2 + 0][0] = t[0]; bh_[bt * 2 + 0][1] = t[2];
                bh_[bt * 2 + 1][0] = t[1]; bh_[bt * 2 + 1][1] = t[3];
                ldsm4(t, u + 3 * (PADT * 2) + off);
                bl_[bt * 2 + 0][0] = t[0]; bl_[bt * 2 + 0][1] = t[2];
                bl_[bt * 2 + 1][0] = t[1]; bl_[bt * 2 + 1][1] = t[3];
            }
            uint32_t a_[4][4];
            #pragma unroll
            for (int mt = 0; mt < 4; mt++)
                ldsm4(a_[mt], u + (wm * 64 + mt * 16 + (lane & 15)) * (PADR * 2) + cb);
            #pragma unroll
            for (int mt = 0; mt < 4; mt++)
                #pragma unroll
                for (int nt = 0; nt < 4; nt++) {
                    mma16816(acc[mt][nt], a_[mt], bh_[nt][0], bh_[nt][1]);
                    mma16816(acc[mt][nt], a_[mt], bl_[nt][0], bl_[nt][1]);
                }
            #pragma unroll
            for (int mt = 0; mt < 4; mt++)
                ldsm4(a_[mt], u + PADT * 2 + (wm * 64 + mt * 16 + (lane & 15)) * (PADR * 2) + cb);
            #pragma unroll
            for (int mt = 0; mt < 4; mt++)
                #pragma unroll
                for (int nt = 0; nt < 4; nt++)
                    mma16816(acc[mt][nt], a_[mt], bh_[nt][0], bh_[nt][1]);
        }
        __syncthreads();
    }

    // ---- epilogue ----
    const int rgrp = lane >> 2;
    const int cgrp = (lane & 3) * 2;
    const float* bp = (EPI == 1 || EPI == 2) ? (bias + (size_t)bn * 128) : (const float*)0;
    #pragma unroll
    for (int mt = 0; mt < 4; mt++) {
        #pragma unroll
        for (int half = 0; half < 2; half++) {
            size_t grow = (size_t)bm * 128 + wm * 64 + mt * 16 + rgrp + half * 8;
            #pragma unroll
            for (int nt = 0; nt < 4; nt++) {
                int lcol = wn * 32 + nt * 8 + cgrp;
                size_t gcol = (size_t)bn * 128 + lcol;
                float v0 = acc[mt][nt][half * 2 + 0];
                float v1 = acc[mt][nt][half * 2 + 1];
                if (EPI == 0) {
                    *(float2*)(C + grow * N + gcol) = make_float2(v0, v1);
                } else if (EPI == 1) {
                    float t0 = v0 + bp[lcol], t1 = v1 + bp[lcol + 1];
                    float g0 = 0.5f * t0 * (1.f + erff(t0 * 0.70710678118654752f));
                    float g1 = 0.5f * t1 * (1.f + erff(t1 * 0.70710678118654752f));
                    *(uint32_t*)(Oh + grow * N + gcol) = packh(g0, g1);
                    *(uint32_t*)(Ol + grow * N + gcol) = packl(g0, g1);
                } else if (EPI == 2) {
                    float2 old = *(float2*)(C + grow * N + gcol);
                    *(float2*)(C + grow * N + gcol) =
                        make_float2(old.x + v0 + bp[lcol], old.y + v1 + bp[lcol + 1]);
                } else {   // EPI == 3: qkv split
                    if (gcol < DIMM) {
                        size_t idx = grow * DIMM + gcol;
                        *(uint32_t*)(Qh + idx) = packh(v0, v1);
                        *(uint32_t*)(Ql + idx) = packl(v0, v1);
                    } else if (gcol < 2 * DIMM) {
                        size_t idx = grow * DIMM + gcol - DIMM;
                        *(uint32_t*)(Kh + idx) = packh(v0, v1);
                        *(uint32_t*)(Kl + idx) = packl(v0, v1);
                    } else {
                        size_t d = gcol - 2 * DIMM;
                        __nv_bfloat16 h0 = __float2bfloat16(v0), h1 = __float2bfloat16(v1);
                        Vh[d * TOK + grow]       = h0;
                        Vh[(d + 1) * TOK + grow] = h1;
                        Vl[d * TOK + grow]       = __float2bfloat16(v0 - __bfloat162float(h0));
                        Vl[(d + 1) * TOK + grow] = __float2bfloat16(v1 - __bfloat162float(h1));
                    }
                }
            }
        }
    }
}

// ---------------- HMMA flash attention, bf16 3-split, fp32 softmax ----------------
// block: 128 q-rows x 1 head; 8 warps, each warp m16 rows. KV tiles of 64.
// smem: 2 stages x {Kh,Kl,Vth,Vtl} 8KB each = 65536 B
#define AT_SMEM 65536

__global__ __launch_bounds__(256) void attn_mma(
    const __nv_bfloat16* __restrict__ qh, const __nv_bfloat16* __restrict__ ql,
    const __nv_bfloat16* __restrict__ kh, const __nv_bfloat16* __restrict__ kl,
    const __nv_bfloat16* __restrict__ vh, const __nv_bfloat16* __restrict__ vl,
    __nv_bfloat16* __restrict__ oh, __nv_bfloat16* __restrict__ ol)
{
    extern __shared__ __align__(1024) char sm[];
    const uint32_t base = smem_u32(sm);
    const int tid = threadIdx.x, wid = tid >> 5, lane = tid & 31;
    const int qb = blockIdx.x, head = blockIdx.y, batch = blockIdx.z;
    const size_t tok0 = (size_t)batch * SEQ;

    // ---- stage Q (hi at base, lo at +16K), extract fragments ----
    {
        const __nv_bfloat16* qhg = qh + (tok0 + qb * 128) * DIMM + head * HD;
        const __nv_bfloat16* qlg = ql + (tok0 + qb * 128) * DIMM + head * HD;
        #pragma unroll
        for (int i = 0; i < 4; i++) {
            int f = tid + 256 * i;
            int r = f >> 3, c = f & 7;
            uint32_t sw = SWZ(r * 128 + c * 16);
            cp16(base + sw,         qhg + (size_t)r * DIMM + c * 8);
            cp16(base + 16384 + sw, qlg + (size_t)r * DIMM + c * 8);
        }
        CP_COMMIT(); CP_WAIT(0);
    }
    __syncthreads();
    uint32_t qfh[4][4], qfl[4][4];
    {
        int rb = (wid * 16 + (lane & 15)) * 128 + (lane >> 4) * 16;
        #pragma unroll
        for (int kt = 0; kt < 4; kt++) {
            ldsm4(qfh[kt], base + SWZ(rb + kt * 32));
            ldsm4(qfl[kt], base + 16384 + SWZ(rb + kt * 32));
        }
    }
    __syncthreads();

    auto loadkv = [&](int it, int st) {
        uint32_t u = base + st * 32768;
        const __nv_bfloat16* kg  = kh + (tok0 + it * 64) * DIMM + head * HD;
        const __nv_bfloat16* lg  = kl + (tok0 + it * 64) * DIMM + head * HD;
        const __nv_bfloat16* vhg = vh + (size_t)(head * HD) * TOK + tok0 + it * 64;
        const __nv_bfloat16* vlg = vl + (size_t)(head * HD) * TOK + tok0 + it * 64;
        #pragma unroll
        for (int i = 0; i < 2; i++) {
            int f = tid + 256 * i;
            int r = f >> 3, c = f & 7;
            uint32_t sw = SWZ(r * 128 + c * 16);
            cp16(u + sw,          kg  + (size_t)r * DIMM + c * 8);
            cp16(u + 8192 + sw,   lg  + (size_t)r * DIMM + c * 8);
            cp16(u + 16384 + sw,  vhg + (size_t)r * TOK + c * 8);
            cp16(u + 24576 + sw,  vlg + (size_t)r * TOK + c * 8);
        }
        CP_COMMIT();
    };

    float m0 = -INFINITY, m1 = -INFINITY, l0 = 0.f, l1 = 0.f;
    float O[8][4];
    #pragma unroll
    for (int i = 0; i < 8; i++)
        #pragma unroll
        for (int j = 0; j < 4; j++) O[i][j] = 0.f;

    loadkv(0, 0);

    for (int it = 0; it < SEQ / 64; it++) {
        int st = it & 1;
        if (it + 1 < SEQ / 64) { loadkv(it + 1, st ^ 1); CP_WAIT(1); }
        else                   { CP_WAIT(0); }
        __syncthreads();
        uint32_t u = base + st * 32768;

        // ---- S = scale * Q K^T (3-split) ----
        float S[8][4];
        #pragma unroll
        for (int i = 0; i < 8; i++)
            #pragma unroll
            for (int j = 0; j < 4; j++) S[i][j] = 0.f;

        #pragma unroll
        for (int kt = 0; kt < 4; kt++) {
            uint32_t th[4][4], tl[4][4];
            #pragma unroll
            for (int g = 0; g < 4; g++) {
                uint32_t sw = SWZ((g * 16 + (lane & 15)) * 128 + kt * 32 + (lane >> 4) * 16);
                ldsm4(th[g], u + sw);
                ldsm4(tl[g], u + 8192 + sw);
            }
            #pragma unroll
            for (int g = 0; g < 4; g++) {
                mma16816(S[2 * g],     qfh[kt], th[g][0], th[g][2]);
                mma16816(S[2 * g + 1], qfh[kt], th[g][1], th[g][3]);
                mma16816(S[2 * g],     qfh[kt], tl[g][0], tl[g][2]);
                mma16816(S[2 * g + 1], qfh[kt], tl[g][1], tl[g][3]);
                mma16816(S[2 * g],     qfl[kt], th[g][0], th[g][2]);
                mma16816(S[2 * g + 1], qfl[kt], th[g][1], th[g][3]);
            }
        }

        // ---- fp32 online softmax (rows r=lane>>2 and r+8) ----
        #pragma unroll
        for (int i = 0; i < 8; i++)
            #pragma unroll
            for (int j = 0; j < 4; j++) S[i][j] *= ATT_SCALE;

        float mx0 = S[0][0], mx1 = S[0][2];
        #pragma unroll
        for (int i = 0; i < 8; i++) {
            mx0 = fmaxf(mx0, fmaxf(S[i][0], S[i][1]));
            mx1 = fmaxf(mx1, fmaxf(S[i][2], S[i][3]));
        }
        mx0 = fmaxf(mx0, __shfl_xor_sync(0xffffffffu, mx0, 1));
        mx0 = fmaxf(mx0, __shfl_xor_sync(0xffffffffu, mx0, 2));
        mx1 = fmaxf(mx1, __shfl_xor_sync(0xffffffffu, mx1, 1));
        mx1 = fmaxf(mx1, __shfl_xor_sync(0xffffffffu, mx1, 2));
        float mn0 = fmaxf(m0, mx0), mn1 = fmaxf(m1, mx1);
        float c0 = __expf(m0 - mn0), c1 = __expf(m1 - mn1);
        m0 = mn0; m1 = mn1;
        float s0 = 0.f, s1 = 0.f;
        #pragma unroll
        for (int i = 0; i < 8; i++) {
            S[i][0] = __expf(S[i][0] - mn0); S[i][1] = __expf(S[i][1] - mn0);
            S[i][2] = __expf(S[i][2] - mn1); S[i][3] = __expf(S[i][3] - mn1);
            s0 += S[i][0] + S[i][1];
            s1 += S[i][2] + S[i][3];
        }
        s0 += __shfl_xor_sync(0xffffffffu, s0, 1);
        s0 += __shfl_xor_sync(0xffffffffu, s0, 2);
        s1 += __shfl_xor_sync(0xffffffffu, s1, 1);
        s1 += __shfl_xor_sync(0xffffffffu, s1, 2);
        l0 = l0 * c0 + s0;
        l1 = l1 * c1 + s1;
        #pragma unroll
        for (int i = 0; i < 8; i++) {
            O[i][0] *= c0; O[i][1] *= c0;
            O[i][2] *= c1; O[i][3] *= c1;
        }

        // ---- O += P V (3-split; P packed from S regs) ----
        #pragma unroll
        for (int kt = 0; kt < 4; kt++) {
            uint32_t ph_[4], pl_[4];
            ph_[0] = packh(S[2 * kt][0], S[2 * kt][1]);
            ph_[1] = packh(S[2 * kt][2], S[2 * kt][3]);
            ph_[2] = packh(S[2 * kt + 1][0], S[2 * kt + 1][1]);
            ph_[3] = packh(S[2 * kt + 1][2], S[2 * kt + 1][3]);
            pl_[0] = packl(S[2 * kt][0], S[2 * kt][1]);
            pl_[1] = packl(S[2 * kt][2], S[2 * kt][3]);
            pl_[2] = packl(S[2 * kt + 1][0], S[2 * kt + 1][1]);
            pl_[3] = packl(S[2 * kt + 1][2], S[2 * kt + 1][3]);
            uint32_t th[4][4], tl[4][4];
            #pragma unroll
            for (int g = 0; g < 4; g++) {
                uint32_t sw = SWZ((g * 16 + (lane & 15)) * 128 + kt * 32 + (lane >> 4) * 16);
                ldsm4(th[g], u + 16384 + sw);
                ldsm4(tl[g], u + 24576 + sw);
            }
            #pragma unroll
            for (int g = 0; g < 4; g++) {
                mma16816(O[2 * g],     ph_, th[g][0], th[g][2]);
                mma16816(O[2 * g + 1], ph_, th[g][1], th[g][3]);
                mma16816(O[2 * g],     ph_, tl[g][0], tl[g][2]);
                mma16816(O[2 * g + 1], ph_, tl[g][1], tl[g][3]);
                mma16816(O[2 * g],     pl_, th[g][0], th[g][2]);
                mma16816(O[2 * g + 1], pl_, th[g][1], th[g][3]);
            }
        }
        __syncthreads();
    }

    // ---- normalize + write hi/lo ----
    float i0 = 1.f / l0, i1 = 1.f / l1;
    size_t row0 = tok0 + (size_t)qb * 128 + wid * 16 + (lane >> 2);
    int colb = head * HD + (lane & 3) * 2;
    #pragma unroll
    for (int nt = 0; nt < 8; nt++) {
        float a = O[nt][0] * i0, b = O[nt][1] * i0;
        float c = O[nt][2] * i1, d = O[nt][3] * i1;
        size_t idx0 = row0 * DIMM + colb + nt * 8;
        size_t idx1 = (row0 + 8) * DIMM + colb + nt * 8;
        *(uint32_t*)(oh + idx0) = packh(a, b);
        *(uint32_t*)(ol + idx0) = packl(a, b);
        *(uint32_t*)(oh + idx1) = packh(c, d);
        *(uint32_t*)(ol + idx1) = packl(c, d);
    }
}

// ---------------- driver ----------------
extern "C" void kernel_launch(void* const* d_in, const int* in_sizes, int n_in,
                              void* d_out, int out_size)
{
    const float* x    = (const float*)d_in[0];
    const float* Wqkv = (const float*)d_in[1];
    const float* Wout = (const float*)d_in[2];
    const float* bout = (const float*)d_in[3];
    const float* ln1g = (const float*)d_in[4];
    const float* ln1b = (const float*)d_in[5];
    const float* ln2g = (const float*)d_in[6];
    const float* ln2b = (const float*)d_in[7];
    const float* W1   = (const float*)d_in[8];
    const float* b1   = (const float*)d_in[9];
    const float* W2   = (const float*)d_in[10];
    const float* b2   = (const float*)d_in[11];
    float* h = (float*)d_out;

    __nv_bfloat16 *ah, *al, *mh, *ml, *wh, *wl, *qh, *ql, *kh, *kl, *vh, *vl;
    cudaGetSymbolAddress((void**)&ah, g_ah);  cudaGetSymbolAddress((void**)&al, g_al);
    cudaGetSymbolAddress((void**)&mh, g_mh);  cudaGetSymbolAddress((void**)&ml, g_ml);
    cudaGetSymbolAddress((void**)&wh, g_wh);  cudaGetSymbolAddress((void**)&wl, g_wl);
    cudaGetSymbolAddress((void**)&qh, g_qh);  cudaGetSymbolAddress((void**)&ql, g_ql);
    cudaGetSymbolAddress((void**)&kh, g_kh);  cudaGetSymbolAddress((void**)&kl, g_kl);
    cudaGetSymbolAddress((void**)&vh, g_vh);  cudaGetSymbolAddress((void**)&vl, g_vl);

    cudaFuncSetAttribute(attn_mma,    cudaFuncAttributeMaxDynamicSharedMemorySize, AT_SMEM);
    cudaFuncSetAttribute(gemm_mma<1>, cudaFuncAttributeMaxDynamicSharedMemorySize, GEMM_SMEM_B);
    cudaFuncSetAttribute(gemm_mma<2>, cudaFuncAttributeMaxDynamicSharedMemorySize, GEMM_SMEM_B);
    cudaFuncSetAttribute(gemm_mma<3>, cudaFuncAttributeMaxDynamicSharedMemorySize, GEMM_SMEM_B);

    copy_kernel<<<TOK, 256>>>((const float4*)x, (float4*)h, TOK * DIMM / 4);

    for (int l = 0; l < DEPTH; l++) {
        // --- attention block ---
        wconv<<<dim3(3 * DIMM / 32, DIMM / 32), dim3(32, 32)>>>(
            Wqkv + (size_t)l * DIMM * 3 * DIMM, DIMM, 3 * DIMM, wh, wl);
        ln_kernel<<<TOK, 256>>>(h, ln1g + (size_t)l * DIMM, ln1b + (size_t)l * DIMM, ah, al);
        gemm_mma<3><<<dim3(3 * DIMM / 128, TOK / 128), 256, GEMM_SMEM_B>>>(
            ah, al, wh, wl, (const float*)0, (float*)0, (__nv_bfloat16*)0, (__nv_bfloat16*)0,
            qh, ql, kh, kl, vh, vl, TOK, 3 * DIMM, DIMM);
        attn_mma<<<dim3(SEQ / 128, HEADS, 2), 256, AT_SMEM>>>(
            qh, ql, kh, kl, vh, vl, ah, al);
        wconv<<<dim3(DIMM / 32, DIMM / 32), dim3(32, 32)>>>(
            Wout + (size_t)l * DIMM * DIMM, DIMM, DIMM, wh, wl);
        gemm_mma<2><<<dim3(DIMM / 128, TOK / 128), 256, GEMM_SMEM_B>>>(
            ah, al, wh, wl, bout + (size_t)l * DIMM, h, (__nv_bfloat16*)0, (__nv_bfloat16*)0,
            (__nv_bfloat16*)0, (__nv_bfloat16*)0, (__nv_bfloat16*)0, (__nv_bfloat16*)0,
            (__nv_bfloat16*)0, (__nv_bfloat16*)0, TOK, DIMM, DIMM);
        // --- ffn block ---
        ln_kernel<<<TOK, 256>>>(h, ln2g + (size_t)l * DIMM, ln2b + (size_t)l * DIMM, ah, al);
        wconv<<<dim3(MLPD / 32, DIMM / 32), dim3(32, 32)>>>(
            W1 + (size_t)l * DIMM * MLPD, DIMM, MLPD, wh, wl);
        gemm_mma<1><<<dim3(MLPD / 128, TOK / 128), 256, GEMM_SMEM_B>>>(
            ah, al, wh, wl, b1 + (size_t)l * MLPD, (float*)0, mh, ml,
            (__nv_bfloat16*)0, (__nv_bfloat16*)0, (__nv_bfloat16*)0, (__nv_bfloat16*)0,
            (__nv_bfloat16*)0, (__nv_bfloat16*)0, TOK, MLPD, DIMM);
        wconv<<<dim3(DIMM / 32, MLPD / 32), dim3(32, 32)>>>(
            W2 + (size_t)l * MLPD * DIMM, MLPD, DIMM, wh, wl);
        gemm_mma<2><<<dim3(DIMM / 128, TOK / 128), 256, GEMM_SMEM_B>>>(
            mh, ml, wh, wl, b2 + (size_t)l * DIMM, h, (__nv_bfloat16*)0, (__nv_bfloat16*)0,
            (__nv_bfloat16*)0, (__nv_bfloat16*)0, (__nv_bfloat16*)0, (__nv_bfloat16*)0,
            (__nv_bfloat16*)0, (__nv_bfloat16*)0, TOK, DIMM, MLPD);
    }
}

// round 5
// speedup vs baseline: 3.1823x; 1.3997x over previous
#include <cuda_runtime.h>
#include <cuda_fp16.h>
#include <math.h>
#include <stdint.h>

#define TOK   4096
#define SEQ   2048
#define DIMM  1024
#define HEADS 16
#define HD    64
#define MLPD  4096
#define DEPTH 6
#define ATT_SCALE 0.03125f

// ---------------- scratch ----------------
__device__ __half g_ah[TOK * DIMM], g_al[TOK * DIMM];    // act A hi/lo (ln out, attn out)
__device__ __half g_mh[TOK * MLPD], g_ml[TOK * MLPD];    // mlp hidden hi/lo
__device__ __half g_w [DIMM * MLPD];                     // transposed weight, single fp16
__device__ __half g_qh[TOK * DIMM], g_ql[TOK * DIMM];    // Q hi/lo [token][dim]
__device__ __half g_k [TOK * DIMM];                      // K single [token][dim]
__device__ __half g_v [DIMM * TOK];                      // V single transposed [dim][token]

// ---------------- PTX helpers ----------------
__device__ __forceinline__ uint32_t smem_u32(const void* p) {
    uint32_t a;
    asm("{ .reg .u64 t; cvta.to.shared.u64 t, %1; cvt.u32.u64 %0, t; }" : "=r"(a) : "l"(p));
    return a;
}
#define SWZ(o) ((o) ^ (((o) >> 3) & 0x70))
__device__ __forceinline__ void cp16(uint32_t dst, const void* src) {
    asm volatile("cp.async.cg.shared.global [%0], [%1], 16;" :: "r"(dst), "l"(src));
}
#define CP_COMMIT()  asm volatile("cp.async.commit_group;")
#define CP_WAIT(n)   asm volatile("cp.async.wait_group " #n ";")

__device__ __forceinline__ void ldsm4(uint32_t* r, uint32_t addr) {
    asm volatile("ldmatrix.sync.aligned.m8n8.x4.shared.b16 {%0,%1,%2,%3}, [%4];"
        : "=r"(r[0]), "=r"(r[1]), "=r"(r[2]), "=r"(r[3]) : "r"(addr));
}
__device__ __forceinline__ void mma16816(float* c, const uint32_t* a, uint32_t b0, uint32_t b1) {
    asm volatile(
        "mma.sync.aligned.m16n8k16.row.col.f32.f16.f16.f32 "
        "{%0,%1,%2,%3}, {%4,%5,%6,%7}, {%8,%9}, {%0,%1,%2,%3};"
        : "+f"(c[0]), "+f"(c[1]), "+f"(c[2]), "+f"(c[3])
        : "r"(a[0]), "r"(a[1]), "r"(a[2]), "r"(a[3]), "r"(b0), "r"(b1));
}
__device__ __forceinline__ uint32_t packh(float a, float b) {
    __half2 t = __floats2half2_rn(a, b);
    return *(uint32_t*)&t;
}
__device__ __forceinline__ uint32_t packl(float a, float b) {
    float ah = __half2float(__float2half(a));
    float bh = __half2float(__float2half(b));
    return packh(a - ah, b - bh);
}

// ---------------- copy ----------------
__global__ void copy_kernel(const float4* __restrict__ src, float4* __restrict__ dst, int n) {
    int i = blockIdx.x * blockDim.x + threadIdx.x;
    if (i < n) dst[i] = src[i];
}

// ---------------- weight convert + transpose: W[K,N] fp32 -> Wt[N,K] fp16 ----------------
__global__ __launch_bounds__(1024) void wconv(const float* __restrict__ W, int K, int N,
                                              __half* __restrict__ T) {
    __shared__ float t[32][33];
    int tx = threadIdx.x, ty = threadIdx.y;
    int n0 = blockIdx.x * 32, k0 = blockIdx.y * 32;
    t[ty][tx] = W[(size_t)(k0 + ty) * N + n0 + tx];
    __syncthreads();
    T[(size_t)(n0 + ty) * K + k0 + tx] = __float2half(t[tx][ty]);
}

// ---------------- layernorm -> fp16 hi/lo ----------------
__global__ __launch_bounds__(256) void ln_kernel(const float* __restrict__ x,
                                                 const float* __restrict__ g,
                                                 const float* __restrict__ b,
                                                 __half* __restrict__ yh,
                                                 __half* __restrict__ yl) {
    int t = blockIdx.x, tid = threadIdx.x;
    const float4* xv = (const float4*)(x + (size_t)t * DIMM);
    float4 v = xv[tid];
    float s  = v.x + v.y + v.z + v.w;
    float s2 = v.x * v.x + v.y * v.y + v.z * v.z + v.w * v.w;
    #pragma unroll
    for (int o = 16; o > 0; o >>= 1) {
        s  += __shfl_xor_sync(0xffffffffu, s,  o);
        s2 += __shfl_xor_sync(0xffffffffu, s2, o);
    }
    __shared__ float rs[8], rs2[8];
    int w = tid >> 5, lane = tid & 31;
    if (lane == 0) { rs[w] = s; rs2[w] = s2; }
    __syncthreads();
    if (tid == 0) {
        float a = 0.f, a2 = 0.f;
        #pragma unroll
        for (int i = 0; i < 8; i++) { a += rs[i]; a2 += rs2[i]; }
        rs[0] = a; rs2[0] = a2;
    }
    __syncthreads();
    float mean = rs[0] * (1.f / DIMM);
    float var  = rs2[0] * (1.f / DIMM) - mean * mean;
    float inv  = rsqrtf(var + 1e-5f);
    float4 gv = ((const float4*)g)[tid];
    float4 bv = ((const float4*)b)[tid];
    float o0 = (v.x - mean) * inv * gv.x + bv.x;
    float o1 = (v.y - mean) * inv * gv.y + bv.y;
    float o2 = (v.z - mean) * inv * gv.z + bv.z;
    float o3 = (v.w - mean) * inv * gv.w + bv.w;
    uint32_t h01 = packh(o0, o1), h23 = packh(o2, o3);
    uint32_t l01 = packl(o0, o1), l23 = packl(o2, o3);
    *(uint2*)(yh + (size_t)t * DIMM + tid * 4) = make_uint2(h01, h23);
    *(uint2*)(yl + (size_t)t * DIMM + tid * 4) = make_uint2(l01, l23);
}

// ---------------- HMMA GEMM, fp16 2-term (AhB + AlB), 3-stage pipeline ----------------
// C[M,N] = A @ B^T (B stored [N,K]); fp32 accum.
// 128x128 CTA tile, BK=32 chunk {Ah, Al, B}; 8 warps 2Mx4N, warp 64x32.
// EPI: 1 bias+gelu->fp16 hi/lo; 2 C += AB+bias; 3 qkv split write
#define PADR 40
#define PADT (128 * PADR)                 // elems per tile
#define GSTG (3 * PADT * 2)               // bytes per stage (30720)
#define GEMM_SMEM_B (3 * GSTG)            // 92160 (3 stages)

template<int EPI>
__global__ __launch_bounds__(256, 2) void gemm_mma(
    const __half* __restrict__ Ah, const __half* __restrict__ Al,
    const __half* __restrict__ B,
    const float* __restrict__ bias, float* __restrict__ C,
    __half* __restrict__ Oh, __half* __restrict__ Ol,
    __half* __restrict__ Qh, __half* __restrict__ Ql,
    __half* __restrict__ Kb, __half* __restrict__ Vb,
    int M, int N, int K)
{
    extern __shared__ __align__(1024) char smg[];
    const uint32_t sb = smem_u32(smg);
    const int tid = threadIdx.x;
    const int wid = tid >> 5, lane = tid & 31;
    const int wm = wid >> 2, wn = wid & 3;
    const int bn = blockIdx.x, bm = blockIdx.y;

    const __half* src3[3] = {
        Ah + (size_t)bm * 128 * K, Al + (size_t)bm * 128 * K, B + (size_t)bn * 128 * K};

    const int NC = K / 32;

    float acc[4][4][4];
    #pragma unroll
    for (int i = 0; i < 4; i++)
        #pragma unroll
        for (int j = 0; j < 4; j++)
            #pragma unroll
            for (int c = 0; c < 4; c++) acc[i][j][c] = 0.f;

    const int lr = tid >> 2, lc = tid & 3;
    auto load_chunk = [&](int kc, int st) {
        uint32_t u = sb + st * GSTG;
        #pragma unroll
        for (int t = 0; t < 3; t++) {
            const __half* g = src3[t] + kc * 32;
            #pragma unroll
            for (int i = 0; i < 2; i++) {
                int r = lr + 64 * i;
                cp16(u + t * (PADT * 2) + r * (PADR * 2) + lc * 16, g + (size_t)r * K + lc * 8);
            }
        }
        CP_COMMIT();
    };

    load_chunk(0, 0);
    load_chunk(1, 1);

    for (int k = 0; k < NC; k++) {
        int st = k % 3;
        if (k == NC - 1) { CP_WAIT(0); } else { CP_WAIT(1); }
        __syncthreads();
        if (k + 2 < NC) load_chunk(k + 2, (k + 2) % 3);

        uint32_t u = sb + st * GSTG;
        const int arow = (lane & 15) * (PADR * 2);
        #pragma unroll
        for (int ks = 0; ks < 2; ks++) {
            int cb = ks * 32 + (lane >> 4) * 16;
            uint32_t b_[4][2];
            #pragma unroll
            for (int bt = 0; bt < 2; bt++) {
                uint32_t t[4];
                ldsm4(t, u + 2 * (PADT * 2) + (wn * 32 + bt * 16) * (PADR * 2) + arow + cb);
                b_[bt * 2 + 0][0] = t[0]; b_[bt * 2 + 0][1] = t[2];
                b_[bt * 2 + 1][0] = t[1]; b_[bt * 2 + 1][1] = t[3];
            }
            uint32_t a_[4][4];
            #pragma unroll
            for (int mt = 0; mt < 4; mt++)
                ldsm4(a_[mt], u + (wm * 64 + mt * 16) * (PADR * 2) + arow + cb);
            #pragma unroll
            for (int mt = 0; mt < 4; mt++)
                #pragma unroll
                for (int nt = 0; nt < 4; nt++)
                    mma16816(acc[mt][nt], a_[mt], b_[nt][0], b_[nt][1]);
            #pragma unroll
            for (int mt = 0; mt < 4; mt++)
                ldsm4(a_[mt], u + PADT * 2 + (wm * 64 + mt * 16) * (PADR * 2) + arow + cb);
            #pragma unroll
            for (int mt = 0; mt < 4; mt++)
                #pragma unroll
                for (int nt = 0; nt < 4; nt++)
                    mma16816(acc[mt][nt], a_[mt], b_[nt][0], b_[nt][1]);
        }
    }

    // ---- epilogue ----
    const int rgrp = lane >> 2;
    const int cgrp = (lane & 3) * 2;
    const float* bp = (EPI == 1 || EPI == 2) ? (bias + (size_t)bn * 128) : (const float*)0;
    #pragma unroll
    for (int mt = 0; mt < 4; mt++) {
        #pragma unroll
        for (int half = 0; half < 2; half++) {
            size_t grow = (size_t)bm * 128 + wm * 64 + mt * 16 + rgrp + half * 8;
            #pragma unroll
            for (int nt = 0; nt < 4; nt++) {
                int lcol = wn * 32 + nt * 8 + cgrp;
                size_t gcol = (size_t)bn * 128 + lcol;
                float v0 = acc[mt][nt][half * 2 + 0];
                float v1 = acc[mt][nt][half * 2 + 1];
                if (EPI == 1) {
                    float t0 = v0 + bp[lcol], t1 = v1 + bp[lcol + 1];
                    float g0 = 0.5f * t0 * (1.f + erff(t0 * 0.70710678118654752f));
                    float g1 = 0.5f * t1 * (1.f + erff(t1 * 0.70710678118654752f));
                    *(uint32_t*)(Oh + grow * N + gcol) = packh(g0, g1);
                    *(uint32_t*)(Ol + grow * N + gcol) = packl(g0, g1);
                } else if (EPI == 2) {
                    float2 old = *(float2*)(C + grow * N + gcol);
                    *(float2*)(C + grow * N + gcol) =
                        make_float2(old.x + v0 + bp[lcol], old.y + v1 + bp[lcol + 1]);
                } else {   // EPI == 3: qkv split
                    if (gcol < DIMM) {
                        size_t idx = grow * DIMM + gcol;
                        *(uint32_t*)(Qh + idx) = packh(v0, v1);
                        *(uint32_t*)(Ql + idx) = packl(v0, v1);
                    } else if (gcol < 2 * DIMM) {
                        *(uint32_t*)(Kb + grow * DIMM + gcol - DIMM) = packh(v0, v1);
                    } else {
                        size_t d = gcol - 2 * DIMM;
                        Vb[d * TOK + grow]       = __float2half(v0);
                        Vb[(d + 1) * TOK + grow] = __float2half(v1);
                    }
                }
            }
        }
    }
}

// ---------------- HMMA flash attention: Q/P split fp16, K/V single fp16 ----------------
// block: 128 q-rows x 1 head; 8 warps x m16. KV tiles of 64; 2 stages x {K 8KB, V 8KB}.
#define AT_SMEM 32768

__global__ __launch_bounds__(256) void attn_mma(
    const __half* __restrict__ qh, const __half* __restrict__ ql,
    const __half* __restrict__ kb, const __half* __restrict__ vb,
    __half* __restrict__ oh, __half* __restrict__ ol)
{
    extern __shared__ __align__(1024) char sm[];
    const uint32_t base = smem_u32(sm);
    const int tid = threadIdx.x, wid = tid >> 5, lane = tid & 31;
    const int qb = blockIdx.x, head = blockIdx.y, batch = blockIdx.z;
    const size_t tok0 = (size_t)batch * SEQ;

    // ---- stage Q hi/lo, extract fragments ----
    {
        const __half* qhg = qh + (tok0 + qb * 128) * DIMM + head * HD;
        const __half* qlg = ql + (tok0 + qb * 128) * DIMM + head * HD;
        #pragma unroll
        for (int i = 0; i < 4; i++) {
            int f = tid + 256 * i;
            int r = f >> 3, c = f & 7;
            uint32_t sw = SWZ(r * 128 + c * 16);
            cp16(base + sw,         qhg + (size_t)r * DIMM + c * 8);
            cp16(base + 16384 + sw, qlg + (size_t)r * DIMM + c * 8);
        }
        CP_COMMIT(); CP_WAIT(0);
    }
    __syncthreads();
    uint32_t qfh[4][4], qfl[4][4];
    {
        int rb = (wid * 16 + (lane & 15)) * 128 + (lane >> 4) * 16;
        #pragma unroll
        for (int kt = 0; kt < 4; kt++) {
            ldsm4(qfh[kt], base + SWZ(rb + kt * 32));
            ldsm4(qfl[kt], base + 16384 + SWZ(rb + kt * 32));
        }
    }
    __syncthreads();

    auto loadkv = [&](int it, int st) {
        uint32_t u = base + st * 16384;
        const __half* kg = kb + (tok0 + it * 64) * DIMM + head * HD;
        const __half* vg = vb + (size_t)(head * HD) * TOK + tok0 + it * 64;
        #pragma unroll
        for (int i = 0; i < 2; i++) {
            int f = tid + 256 * i;
            int r = f >> 3, c = f & 7;
            uint32_t sw = SWZ(r * 128 + c * 16);
            cp16(u + sw,        kg + (size_t)r * DIMM + c * 8);
            cp16(u + 8192 + sw, vg + (size_t)r * TOK + c * 8);
        }
        CP_COMMIT();
    };

    float m0 = -INFINITY, m1 = -INFINITY, l0 = 0.f, l1 = 0.f;
    float O[8][4];
    #pragma unroll
    for (int i = 0; i < 8; i++)
        #pragma unroll
        for (int j = 0; j < 4; j++) O[i][j] = 0.f;

    loadkv(0, 0);

    for (int it = 0; it < SEQ / 64; it++) {
        int st = it & 1;
        if (it + 1 < SEQ / 64) { loadkv(it + 1, st ^ 1); CP_WAIT(1); }
        else                   { CP_WAIT(0); }
        __syncthreads();
        uint32_t u = base + st * 16384;

        // ---- S = scale * Q K^T (2-term: Qh K + Ql K) ----
        float S[8][4];
        #pragma unroll
        for (int i = 0; i < 8; i++)
            #pragma unroll
            for (int j = 0; j < 4; j++) S[i][j] = 0.f;

        #pragma unroll
        for (int kt = 0; kt < 4; kt++) {
            uint32_t th[4][4];
            #pragma unroll
            for (int g = 0; g < 4; g++)
                ldsm4(th[g], u + SWZ((g * 16 + (lane & 15)) * 128 + kt * 32 + (lane >> 4) * 16));
            #pragma unroll
            for (int g = 0; g < 4; g++) {
                mma16816(S[2 * g],     qfh[kt], th[g][0], th[g][2]);
                mma16816(S[2 * g + 1], qfh[kt], th[g][1], th[g][3]);
                mma16816(S[2 * g],     qfl[kt], th[g][0], th[g][2]);
                mma16816(S[2 * g + 1], qfl[kt], th[g][1], th[g][3]);
            }
        }

        // ---- fp32 online softmax ----
        #pragma unroll
        for (int i = 0; i < 8; i++)
            #pragma unroll
            for (int j = 0; j < 4; j++) S[i][j] *= ATT_SCALE;

        float mx0 = S[0][0], mx1 = S[0][2];
        #pragma unroll
        for (int i = 0; i < 8; i++) {
            mx0 = fmaxf(mx0, fmaxf(S[i][0], S[i][1]));
            mx1 = fmaxf(mx1, fmaxf(S[i][2], S[i][3]));
        }
        mx0 = fmaxf(mx0, __shfl_xor_sync(0xffffffffu, mx0, 1));
        mx0 = fmaxf(mx0, __shfl_xor_sync(0xffffffffu, mx0, 2));
        mx1 = fmaxf(mx1, __shfl_xor_sync(0xffffffffu, mx1, 1));
        mx1 = fmaxf(mx1, __shfl_xor_sync(0xffffffffu, mx1, 2));
        float mn0 = fmaxf(m0, mx0), mn1 = fmaxf(m1, mx1);
        float c0 = __expf(m0 - mn0), c1 = __expf(m1 - mn1);
        m0 = mn0; m1 = mn1;
        float s0 = 0.f, s1 = 0.f;
        #pragma unroll
        for (int i = 0; i < 8; i++) {
            S[i][0] = __expf(S[i][0] - mn0); S[i][1] = __expf(S[i][1] - mn0);
            S[i][2] = __expf(S[i][2] - mn1); S[i][3] = __expf(S[i][3] - mn1);
            s0 += S[i][0] + S[i][1];
            s1 += S[i][2] + S[i][3];
        }
        s0 += __shfl_xor_sync(0xffffffffu, s0, 1);
        s0 += __shfl_xor_sync(0xffffffffu, s0, 2);
        s1 += __shfl_xor_sync(0xffffffffu, s1, 1);
        s1 += __shfl_xor_sync(0xffffffffu, s1, 2);
        l0 = l0 * c0 + s0;
        l1 = l1 * c1 + s1;
        #pragma unroll
        for (int i = 0; i < 8; i++) {
            O[i][0] *= c0; O[i][1] *= c0;
            O[i][2] *= c1; O[i][3] *= c1;
        }

        // ---- O += P V (P split hi/lo in-register, V single) ----
        #pragma unroll
        for (int kt = 0; kt < 4; kt++) {
            uint32_t ph_[4], pl_[4];
            ph_[0] = packh(S[2 * kt][0], S[2 * kt][1]);
            ph_[1] = packh(S[2 * kt][2], S[2 * kt][3]);
            ph_[2] = packh(S[2 * kt + 1][0], S[2 * kt + 1][1]);
            ph_[3] = packh(S[2 * kt + 1][2], S[2 * kt + 1][3]);
            pl_[0] = packl(S[2 * kt][0], S[2 * kt][1]);
            pl_[1] = packl(S[2 * kt][2], S[2 * kt][3]);
            pl_[2] = packl(S[2 * kt + 1][0], S[2 * kt + 1][1]);
            pl_[3] = packl(S[2 * kt + 1][2], S[2 * kt + 1][3]);
            uint32_t tv[4][4];
            #pragma unroll
            for (int g = 0; g < 4; g++)
                ldsm4(tv[g], u + 8192 + SWZ((g * 16 + (lane & 15)) * 128 + kt * 32 + (lane >> 4) * 16));
            #pragma unroll
            for (int g = 0; g < 4; g++) {
                mma16816(O[2 * g],     ph_, tv[g][0], tv[g][2]);
                mma16816(O[2 * g + 1], ph_, tv[g][1], tv[g][3]);
                mma16816(O[2 * g],     pl_, tv[g][0], tv[g][2]);
                mma16816(O[2 * g + 1], pl_, tv[g][1], tv[g][3]);
            }
        }
        __syncthreads();
    }

    // ---- normalize + write hi/lo ----
    float i0 = 1.f / l0, i1 = 1.f / l1;
    size_t row0 = tok0 + (size_t)qb * 128 + wid * 16 + (lane >> 2);
    int colb = head * HD + (lane & 3) * 2;
    #pragma unroll
    for (int nt = 0; nt < 8; nt++) {
        float a = O[nt][0] * i0, b = O[nt][1] * i0;
        float c = O[nt][2] * i1, d = O[nt][3] * i1;
        size_t idx0 = row0 * DIMM + colb + nt * 8;
        size_t idx1 = (row0 + 8) * DIMM + colb + nt * 8;
        *(uint32_t*)(oh + idx0) = packh(a, b);
        *(uint32_t*)(ol + idx0) = packl(a, b);
        *(uint32_t*)(oh + idx1) = packh(c, d);
        *(uint32_t*)(ol + idx1) = packl(c, d);
    }
}

// ---------------- driver ----------------
extern "C" void kernel_launch(void* const* d_in, const int* in_sizes, int n_in,
                              void* d_out, int out_size)
{
    const float* x    = (const float*)d_in[0];
    const float* Wqkv = (const float*)d_in[1];
    const float* Wout = (const float*)d_in[2];
    const float* bout = (const float*)d_in[3];
    const float* ln1g = (const float*)d_in[4];
    const float* ln1b = (const float*)d_in[5];
    const float* ln2g = (const float*)d_in[6];
    const float* ln2b = (const float*)d_in[7];
    const float* W1   = (const float*)d_in[8];
    const float* b1   = (const float*)d_in[9];
    const float* W2   = (const float*)d_in[10];
    const float* b2   = (const float*)d_in[11];
    float* h = (float*)d_out;

    __half *ah, *al, *mh, *ml, *w, *qh, *ql, *kb, *vb;
    cudaGetSymbolAddress((void**)&ah, g_ah);  cudaGetSymbolAddress((void**)&al, g_al);
    cudaGetSymbolAddress((void**)&mh, g_mh);  cudaGetSymbolAddress((void**)&ml, g_ml);
    cudaGetSymbolAddress((void**)&w,  g_w);
    cudaGetSymbolAddress((void**)&qh, g_qh);  cudaGetSymbolAddress((void**)&ql, g_ql);
    cudaGetSymbolAddress((void**)&kb, g_k);   cudaGetSymbolAddress((void**)&vb, g_v);

    cudaFuncSetAttribute(attn_mma,    cudaFuncAttributeMaxDynamicSharedMemorySize, AT_SMEM);
    cudaFuncSetAttribute(gemm_mma<1>, cudaFuncAttributeMaxDynamicSharedMemorySize, GEMM_SMEM_B);
    cudaFuncSetAttribute(gemm_mma<2>, cudaFuncAttributeMaxDynamicSharedMemorySize, GEMM_SMEM_B);
    cudaFuncSetAttribute(gemm_mma<3>, cudaFuncAttributeMaxDynamicSharedMemorySize, GEMM_SMEM_B);

    copy_kernel<<<TOK, 256>>>((const float4*)x, (float4*)h, TOK * DIMM / 4);

    for (int l = 0; l < DEPTH; l++) {
        // --- attention block ---
        wconv<<<dim3(3 * DIMM / 32, DIMM / 32), dim3(32, 32)>>>(
            Wqkv + (size_t)l * DIMM * 3 * DIMM, DIMM, 3 * DIMM, w);
        ln_kernel<<<TOK, 256>>>(h, ln1g + (size_t)l * DIMM, ln1b + (size_t)l * DIMM, ah, al);
        gemm_mma<3><<<dim3(3 * DIMM / 128, TOK / 128), 256, GEMM_SMEM_B>>>(
            ah, al, w, (const float*)0, (float*)0, (__half*)0, (__half*)0,
            qh, ql, kb, vb, TOK, 3 * DIMM, DIMM);
        attn_mma<<<dim3(SEQ / 128, HEADS, 2), 256, AT_SMEM>>>(qh, ql, kb, vb, ah, al);
        wconv<<<dim3(DIMM / 32, DIMM / 32), dim3(32, 32)>>>(
            Wout + (size_t)l * DIMM * DIMM, DIMM, DIMM, w);
        gemm_mma<2><<<dim3(DIMM / 128, TOK / 128), 256, GEMM_SMEM_B>>>(
            ah, al, w, bout + (size_t)l * DIMM, h, (__half*)0, (__half*)0,
            (__half*)0, (__half*)0, (__half*)0, (__half*)0, TOK, DIMM, DIMM);
        // --- ffn block ---
        ln_kernel<<<TOK, 256>>>(h, ln2g + (size_t)l * DIMM, ln2b + (size_t)l * DIMM, ah, al);
        wconv<<<dim3(MLPD / 32, DIMM / 32), dim3(32, 32)>>>(
            W1 + (size_t)l * DIMM * MLPD, DIMM, MLPD, w);
        gemm_mma<1><<<dim3(MLPD / 128, TOK / 128), 256, GEMM_SMEM_B>>>(
            ah, al, w, b1 + (size_t)l * MLPD, (float*)0, mh, ml,
            (__half*)0, (__half*)0, (__half*)0, (__half*)0, TOK, MLPD, DIMM);
        wconv<<<dim3(DIMM / 32, MLPD / 32), dim3(32, 32)>>>(
            W2 + (size_t)l * MLPD * DIMM, MLPD, DIMM, w);
        gemm_mma<2><<<dim3(DIMM / 128, TOK / 128), 256, GEMM_SMEM_B>>>(
            mh, ml, w, b2 + (size_t)l * DIMM, h, (__half*)0, (__half*)0,
            (__half*)0, (__half*)0, (__half*)0, (__half*)0, TOK, DIMM, MLPD);
    }
}

// round 6
// speedup vs baseline: 3.5950x; 1.1297x over previous
#include <cuda_runtime.h>
#include <cuda_fp16.h>
#include <math.h>
#include <stdint.h>

#define TOK   4096
#define SEQ   2048
#define DIMM  1024
#define HEADS 16
#define HD    64
#define MLPD  4096
#define DEPTH 6
#define ATT_SCALE 0.03125f

// ---------------- scratch ----------------
__device__ __half g_ah[TOK * DIMM], g_al[TOK * DIMM];    // act A hi/lo (ln out, attn out)
__device__ __half g_mh[TOK * MLPD], g_ml[TOK * MLPD];    // mlp hidden hi/lo
__device__ __half g_w [DIMM * MLPD];                     // transposed weight, single fp16
__device__ __half g_q [TOK * DIMM];                      // Q single [token][dim]
__device__ __half g_k [TOK * DIMM];                      // K single [token][dim]
__device__ __half g_v [DIMM * TOK];                      // V single transposed [dim][token]

// ---------------- PTX helpers ----------------
__device__ __forceinline__ uint32_t smem_u32(const void* p) {
    uint32_t a;
    asm("{ .reg .u64 t; cvta.to.shared.u64 t, %1; cvt.u32.u64 %0, t; }" : "=r"(a) : "l"(p));
    return a;
}
#define SWZ(o) ((o) ^ (((o) >> 3) & 0x70))
__device__ __forceinline__ void cp16(uint32_t dst, const void* src) {
    asm volatile("cp.async.cg.shared.global [%0], [%1], 16;" :: "r"(dst), "l"(src));
}
#define CP_COMMIT()  asm volatile("cp.async.commit_group;")
#define CP_WAIT(n)   asm volatile("cp.async.wait_group " #n ";")

__device__ __forceinline__ void ldsm4(uint32_t* r, uint32_t addr) {
    asm volatile("ldmatrix.sync.aligned.m8n8.x4.shared.b16 {%0,%1,%2,%3}, [%4];"
        : "=r"(r[0]), "=r"(r[1]), "=r"(r[2]), "=r"(r[3]) : "r"(addr));
}
__device__ __forceinline__ void mma16816(float* c, const uint32_t* a, uint32_t b0, uint32_t b1) {
    asm volatile(
        "mma.sync.aligned.m16n8k16.row.col.f32.f16.f16.f32 "
        "{%0,%1,%2,%3}, {%4,%5,%6,%7}, {%8,%9}, {%0,%1,%2,%3};"
        : "+f"(c[0]), "+f"(c[1]), "+f"(c[2]), "+f"(c[3])
        : "r"(a[0]), "r"(a[1]), "r"(a[2]), "r"(a[3]), "r"(b0), "r"(b1));
}
__device__ __forceinline__ uint32_t packh(float a, float b) {
    __half2 t = __floats2half2_rn(a, b);
    return *(uint32_t*)&t;
}
__device__ __forceinline__ uint32_t packl(float a, float b) {
    float ah = __half2float(__float2half(a));
    float bh = __half2float(__float2half(b));
    return packh(a - ah, b - bh);
}

// ---------------- copy ----------------
__global__ void copy_kernel(const float4* __restrict__ src, float4* __restrict__ dst, int n) {
    int i = blockIdx.x * blockDim.x + threadIdx.x;
    if (i < n) dst[i] = src[i];
}

// ---------------- weight convert + transpose: W[K,N] fp32 -> Wt[N,K] fp16 ----------------
__global__ __launch_bounds__(1024) void wconv(const float* __restrict__ W, int K, int N,
                                              __half* __restrict__ T) {
    __shared__ float t[32][33];
    int tx = threadIdx.x, ty = threadIdx.y;
    int n0 = blockIdx.x * 32, k0 = blockIdx.y * 32;
    t[ty][tx] = W[(size_t)(k0 + ty) * N + n0 + tx];
    __syncthreads();
    T[(size_t)(n0 + ty) * K + k0 + tx] = __float2half(t[tx][ty]);
}

// ---------------- layernorm -> fp16 hi/lo ----------------
__global__ __launch_bounds__(256) void ln_kernel(const float* __restrict__ x,
                                                 const float* __restrict__ g,
                                                 const float* __restrict__ b,
                                                 __half* __restrict__ yh,
                                                 __half* __restrict__ yl) {
    int t = blockIdx.x, tid = threadIdx.x;
    const float4* xv = (const float4*)(x + (size_t)t * DIMM);
    float4 v = xv[tid];
    float s  = v.x + v.y + v.z + v.w;
    float s2 = v.x * v.x + v.y * v.y + v.z * v.z + v.w * v.w;
    #pragma unroll
    for (int o = 16; o > 0; o >>= 1) {
        s  += __shfl_xor_sync(0xffffffffu, s,  o);
        s2 += __shfl_xor_sync(0xffffffffu, s2, o);
    }
    __shared__ float rs[8], rs2[8];
    int w = tid >> 5, lane = tid & 31;
    if (lane == 0) { rs[w] = s; rs2[w] = s2; }
    __syncthreads();
    if (tid == 0) {
        float a = 0.f, a2 = 0.f;
        #pragma unroll
        for (int i = 0; i < 8; i++) { a += rs[i]; a2 += rs2[i]; }
        rs[0] = a; rs2[0] = a2;
    }
    __syncthreads();
    float mean = rs[0] * (1.f / DIMM);
    float var  = rs2[0] * (1.f / DIMM) - mean * mean;
    float inv  = rsqrtf(var + 1e-5f);
    float4 gv = ((const float4*)g)[tid];
    float4 bv = ((const float4*)b)[tid];
    float o0 = (v.x - mean) * inv * gv.x + bv.x;
    float o1 = (v.y - mean) * inv * gv.y + bv.y;
    float o2 = (v.z - mean) * inv * gv.z + bv.z;
    float o3 = (v.w - mean) * inv * gv.w + bv.w;
    uint32_t h01 = packh(o0, o1), h23 = packh(o2, o3);
    uint32_t l01 = packl(o0, o1), l23 = packl(o2, o3);
    *(uint2*)(yh + (size_t)t * DIMM + tid * 4) = make_uint2(h01, h23);
    *(uint2*)(yl + (size_t)t * DIMM + tid * 4) = make_uint2(l01, l23);
}

// ---------------- HMMA GEMM, fp16 2-term (AhB + AlB), 3-stage pipeline ----------------
// C[M,N] = A @ B^T (B stored [N,K]); fp32 accum.
// 128x128 CTA tile, BK=32 chunk {Ah, Al, B}; 8 warps 2Mx4N, warp 64x32.
// EPI: 1 bias+gelu->fp16 hi/lo; 2 C += AB+bias; 3 qkv split write (Q single)
#define PADR 40
#define PADT (128 * PADR)                 // elems per tile
#define GSTG (3 * PADT * 2)               // bytes per stage (30720)
#define GEMM_SMEM_B (3 * GSTG)            // 92160 (3 stages)

template<int EPI>
__global__ __launch_bounds__(256, 2) void gemm_mma(
    const __half* __restrict__ Ah, const __half* __restrict__ Al,
    const __half* __restrict__ B,
    const float* __restrict__ bias, float* __restrict__ C,
    __half* __restrict__ Oh, __half* __restrict__ Ol,
    __half* __restrict__ Qb, __half* __restrict__ Kb, __half* __restrict__ Vb,
    int M, int N, int K)
{
    extern __shared__ __align__(1024) char smg[];
    const uint32_t sb = smem_u32(smg);
    const int tid = threadIdx.x;
    const int wid = tid >> 5, lane = tid & 31;
    const int wm = wid >> 2, wn = wid & 3;
    const int bn = blockIdx.x, bm = blockIdx.y;

    const __half* src3[3] = {
        Ah + (size_t)bm * 128 * K, Al + (size_t)bm * 128 * K, B + (size_t)bn * 128 * K};

    const int NC = K / 32;

    float acc[4][4][4];
    #pragma unroll
    for (int i = 0; i < 4; i++)
        #pragma unroll
        for (int j = 0; j < 4; j++)
            #pragma unroll
            for (int c = 0; c < 4; c++) acc[i][j][c] = 0.f;

    const int lr = tid >> 2, lc = tid & 3;
    auto load_chunk = [&](int kc, int st) {
        uint32_t u = sb + st * GSTG;
        #pragma unroll
        for (int t = 0; t < 3; t++) {
            const __half* g = src3[t] + kc * 32;
            #pragma unroll
            for (int i = 0; i < 2; i++) {
                int r = lr + 64 * i;
                cp16(u + t * (PADT * 2) + r * (PADR * 2) + lc * 16, g + (size_t)r * K + lc * 8);
            }
        }
        CP_COMMIT();
    };

    load_chunk(0, 0);
    load_chunk(1, 1);

    for (int k = 0; k < NC; k++) {
        int st = k % 3;
        if (k == NC - 1) { CP_WAIT(0); } else { CP_WAIT(1); }
        __syncthreads();
        if (k + 2 < NC) load_chunk(k + 2, (k + 2) % 3);

        uint32_t u = sb + st * GSTG;
        const int arow = (lane & 15) * (PADR * 2);
        #pragma unroll
        for (int ks = 0; ks < 2; ks++) {
            int cb = ks * 32 + (lane >> 4) * 16;
            uint32_t b_[4][2];
            #pragma unroll
            for (int bt = 0; bt < 2; bt++) {
                uint32_t t[4];
                ldsm4(t, u + 2 * (PADT * 2) + (wn * 32 + bt * 16) * (PADR * 2) + arow + cb);
                b_[bt * 2 + 0][0] = t[0]; b_[bt * 2 + 0][1] = t[2];
                b_[bt * 2 + 1][0] = t[1]; b_[bt * 2 + 1][1] = t[3];
            }
            uint32_t a_[4][4];
            #pragma unroll
            for (int mt = 0; mt < 4; mt++)
                ldsm4(a_[mt], u + (wm * 64 + mt * 16) * (PADR * 2) + arow + cb);
            #pragma unroll
            for (int mt = 0; mt < 4; mt++)
                #pragma unroll
                for (int nt = 0; nt < 4; nt++)
                    mma16816(acc[mt][nt], a_[mt], b_[nt][0], b_[nt][1]);
            #pragma unroll
            for (int mt = 0; mt < 4; mt++)
                ldsm4(a_[mt], u + PADT * 2 + (wm * 64 + mt * 16) * (PADR * 2) + arow + cb);
            #pragma unroll
            for (int mt = 0; mt < 4; mt++)
                #pragma unroll
                for (int nt = 0; nt < 4; nt++)
                    mma16816(acc[mt][nt], a_[mt], b_[nt][0], b_[nt][1]);
        }
    }

    // ---- epilogue ----
    const int rgrp = lane >> 2;
    const int cgrp = (lane & 3) * 2;
    const float* bp = (EPI == 1 || EPI == 2) ? (bias + (size_t)bn * 128) : (const float*)0;
    #pragma unroll
    for (int mt = 0; mt < 4; mt++) {
        #pragma unroll
        for (int half = 0; half < 2; half++) {
            size_t grow = (size_t)bm * 128 + wm * 64 + mt * 16 + rgrp + half * 8;
            #pragma unroll
            for (int nt = 0; nt < 4; nt++) {
                int lcol = wn * 32 + nt * 8 + cgrp;
                size_t gcol = (size_t)bn * 128 + lcol;
                float v0 = acc[mt][nt][half * 2 + 0];
                float v1 = acc[mt][nt][half * 2 + 1];
                if (EPI == 1) {
                    float t0 = v0 + bp[lcol], t1 = v1 + bp[lcol + 1];
                    float g0 = 0.5f * t0 * (1.f + erff(t0 * 0.70710678118654752f));
                    float g1 = 0.5f * t1 * (1.f + erff(t1 * 0.70710678118654752f));
                    *(uint32_t*)(Oh + grow * N + gcol) = packh(g0, g1);
                    *(uint32_t*)(Ol + grow * N + gcol) = packl(g0, g1);
                } else if (EPI == 2) {
                    float2 old = *(float2*)(C + grow * N + gcol);
                    *(float2*)(C + grow * N + gcol) =
                        make_float2(old.x + v0 + bp[lcol], old.y + v1 + bp[lcol + 1]);
                } else {   // EPI == 3: qkv split (Q/K/V all single fp16)
                    if (gcol < DIMM) {
                        *(uint32_t*)(Qb + grow * DIMM + gcol) = packh(v0, v1);
                    } else if (gcol < 2 * DIMM) {
                        *(uint32_t*)(Kb + grow * DIMM + gcol - DIMM) = packh(v0, v1);
                    } else {
                        size_t d = gcol - 2 * DIMM;
                        Vb[d * TOK + grow]       = __float2half(v0);
                        Vb[(d + 1) * TOK + grow] = __float2half(v1);
                    }
                }
            }
        }
    }
}

// ---------------- HMMA flash attention: Q, K, V, P all single fp16; fp32 softmax ----------------
// block: 128 q-rows x 1 head; 8 warps x m16. KV tiles of 64; 3 stages x {K 8KB, V 8KB}.
#define AT_SMEM 49152

__global__ __launch_bounds__(256) void attn_mma(
    const __half* __restrict__ qb,
    const __half* __restrict__ kb, const __half* __restrict__ vb,
    __half* __restrict__ oh, __half* __restrict__ ol)
{
    extern __shared__ __align__(1024) char sm[];
    const uint32_t base = smem_u32(sm);
    const int tid = threadIdx.x, wid = tid >> 5, lane = tid & 31;
    const int qb_ = blockIdx.x, head = blockIdx.y, batch = blockIdx.z;
    const size_t tok0 = (size_t)batch * SEQ;

    // ---- stage Q, extract fragments ----
    {
        const __half* qg = qb + (tok0 + qb_ * 128) * DIMM + head * HD;
        #pragma unroll
        for (int i = 0; i < 4; i++) {
            int f = tid + 256 * i;
            int r = f >> 3, c = f & 7;
            cp16(base + SWZ(r * 128 + c * 16), qg + (size_t)r * DIMM + c * 8);
        }
        CP_COMMIT(); CP_WAIT(0);
    }
    __syncthreads();
    uint32_t qf[4][4];
    {
        int rb = (wid * 16 + (lane & 15)) * 128 + (lane >> 4) * 16;
        #pragma unroll
        for (int kt = 0; kt < 4; kt++)
            ldsm4(qf[kt], base + SWZ(rb + kt * 32));
    }
    __syncthreads();

    auto loadkv = [&](int it, int st) {
        uint32_t u = base + st * 16384;
        const __half* kg = kb + (tok0 + it * 64) * DIMM + head * HD;
        const __half* vg = vb + (size_t)(head * HD) * TOK + tok0 + it * 64;
        #pragma unroll
        for (int i = 0; i < 2; i++) {
            int f = tid + 256 * i;
            int r = f >> 3, c = f & 7;
            uint32_t sw = SWZ(r * 128 + c * 16);
            cp16(u + sw,        kg + (size_t)r * DIMM + c * 8);
            cp16(u + 8192 + sw, vg + (size_t)r * TOK + c * 8);
        }
        CP_COMMIT();
    };

    float m0 = -INFINITY, m1 = -INFINITY, l0 = 0.f, l1 = 0.f;
    float O[8][4];
    #pragma unroll
    for (int i = 0; i < 8; i++)
        #pragma unroll
        for (int j = 0; j < 4; j++) O[i][j] = 0.f;

    loadkv(0, 0);
    loadkv(1, 1);

    const int NT = SEQ / 64;
    for (int it = 0; it < NT; it++) {
        int st = it % 3;
        if (it == NT - 1) { CP_WAIT(0); } else { CP_WAIT(1); }
        __syncthreads();
        if (it + 2 < NT) loadkv(it + 2, (it + 2) % 3);
        uint32_t u = base + st * 16384;

        // ---- S = scale * Q K^T (single term) ----
        float S[8][4];
        #pragma unroll
        for (int i = 0; i < 8; i++)
            #pragma unroll
            for (int j = 0; j < 4; j++) S[i][j] = 0.f;

        #pragma unroll
        for (int kt = 0; kt < 4; kt++) {
            uint32_t th[4][4];
            #pragma unroll
            for (int g = 0; g < 4; g++)
                ldsm4(th[g], u + SWZ((g * 16 + (lane & 15)) * 128 + kt * 32 + (lane >> 4) * 16));
            #pragma unroll
            for (int g = 0; g < 4; g++) {
                mma16816(S[2 * g],     qf[kt], th[g][0], th[g][2]);
                mma16816(S[2 * g + 1], qf[kt], th[g][1], th[g][3]);
            }
        }

        // ---- fp32 online softmax (rows r=lane>>2 and r+8) ----
        #pragma unroll
        for (int i = 0; i < 8; i++)
            #pragma unroll
            for (int j = 0; j < 4; j++) S[i][j] *= ATT_SCALE;

        float mx0 = S[0][0], mx1 = S[0][2];
        #pragma unroll
        for (int i = 0; i < 8; i++) {
            mx0 = fmaxf(mx0, fmaxf(S[i][0], S[i][1]));
            mx1 = fmaxf(mx1, fmaxf(S[i][2], S[i][3]));
        }
        mx0 = fmaxf(mx0, __shfl_xor_sync(0xffffffffu, mx0, 1));
        mx0 = fmaxf(mx0, __shfl_xor_sync(0xffffffffu, mx0, 2));
        mx1 = fmaxf(mx1, __shfl_xor_sync(0xffffffffu, mx1, 1));
        mx1 = fmaxf(mx1, __shfl_xor_sync(0xffffffffu, mx1, 2));
        float mn0 = fmaxf(m0, mx0), mn1 = fmaxf(m1, mx1);
        float c0 = __expf(m0 - mn0), c1 = __expf(m1 - mn1);
        m0 = mn0; m1 = mn1;
        float s0 = 0.f, s1 = 0.f;
        #pragma unroll
        for (int i = 0; i < 8; i++) {
            S[i][0] = __expf(S[i][0] - mn0); S[i][1] = __expf(S[i][1] - mn0);
            S[i][2] = __expf(S[i][2] - mn1); S[i][3] = __expf(S[i][3] - mn1);
            s0 += S[i][0] + S[i][1];
            s1 += S[i][2] + S[i][3];
        }
        s0 += __shfl_xor_sync(0xffffffffu, s0, 1);
        s0 += __shfl_xor_sync(0xffffffffu, s0, 2);
        s1 += __shfl_xor_sync(0xffffffffu, s1, 1);
        s1 += __shfl_xor_sync(0xffffffffu, s1, 2);
        l0 = l0 * c0 + s0;
        l1 = l1 * c1 + s1;
        #pragma unroll
        for (int i = 0; i < 8; i++) {
            O[i][0] *= c0; O[i][1] *= c0;
            O[i][2] *= c1; O[i][3] *= c1;
        }

        // ---- O += P V (P single fp16, packed in-register) ----
        #pragma unroll
        for (int kt = 0; kt < 4; kt++) {
            uint32_t p_[4];
            p_[0] = packh(S[2 * kt][0], S[2 * kt][1]);
            p_[1] = packh(S[2 * kt][2], S[2 * kt][3]);
            p_[2] = packh(S[2 * kt + 1][0], S[2 * kt + 1][1]);
            p_[3] = packh(S[2 * kt + 1][2], S[2 * kt + 1][3]);
            uint32_t tv[4][4];
            #pragma unroll
            for (int g = 0; g < 4; g++)
                ldsm4(tv[g], u + 8192 + SWZ((g * 16 + (lane & 15)) * 128 + kt * 32 + (lane >> 4) * 16));
            #pragma unroll
            for (int g = 0; g < 4; g++) {
                mma16816(O[2 * g],     p_, tv[g][0], tv[g][2]);
                mma16816(O[2 * g + 1], p_, tv[g][1], tv[g][3]);
            }
        }
    }

    // ---- normalize + write hi/lo ----
    float i0 = 1.f / l0, i1 = 1.f / l1;
    size_t row0 = tok0 + (size_t)qb_ * 128 + wid * 16 + (lane >> 2);
    int colb = head * HD + (lane & 3) * 2;
    #pragma unroll
    for (int nt = 0; nt < 8; nt++) {
        float a = O[nt][0] * i0, b = O[nt][1] * i0;
        float c = O[nt][2] * i1, d = O[nt][3] * i1;
        size_t idx0 = row0 * DIMM + colb + nt * 8;
        size_t idx1 = (row0 + 8) * DIMM + colb + nt * 8;
        *(uint32_t*)(oh + idx0) = packh(a, b);
        *(uint32_t*)(ol + idx0) = packl(a, b);
        *(uint32_t*)(oh + idx1) = packh(c, d);
        *(uint32_t*)(ol + idx1) = packl(c, d);
    }
}

// ---------------- driver ----------------
extern "C" void kernel_launch(void* const* d_in, const int* in_sizes, int n_in,
                              void* d_out, int out_size)
{
    const float* x    = (const float*)d_in[0];
    const float* Wqkv = (const float*)d_in[1];
    const float* Wout = (const float*)d_in[2];
    const float* bout = (const float*)d_in[3];
    const float* ln1g = (const float*)d_in[4];
    const float* ln1b = (const float*)d_in[5];
    const float* ln2g = (const float*)d_in[6];
    const float* ln2b = (const float*)d_in[7];
    const float* W1   = (const float*)d_in[8];
    const float* b1   = (const float*)d_in[9];
    const float* W2   = (const float*)d_in[10];
    const float* b2   = (const float*)d_in[11];
    float* h = (float*)d_out;

    __half *ah, *al, *mh, *ml, *w, *qb, *kb, *vb;
    cudaGetSymbolAddress((void**)&ah, g_ah);  cudaGetSymbolAddress((void**)&al, g_al);
    cudaGetSymbolAddress((void**)&mh, g_mh);  cudaGetSymbolAddress((void**)&ml, g_ml);
    cudaGetSymbolAddress((void**)&w,  g_w);
    cudaGetSymbolAddress((void**)&qb, g_q);
    cudaGetSymbolAddress((void**)&kb, g_k);   cudaGetSymbolAddress((void**)&vb, g_v);

    cudaFuncSetAttribute(attn_mma,    cudaFuncAttributeMaxDynamicSharedMemorySize, AT_SMEM);
    cudaFuncSetAttribute(gemm_mma<1>, cudaFuncAttributeMaxDynamicSharedMemorySize, GEMM_SMEM_B);
    cudaFuncSetAttribute(gemm_mma<2>, cudaFuncAttributeMaxDynamicSharedMemorySize, GEMM_SMEM_B);
    cudaFuncSetAttribute(gemm_mma<3>, cudaFuncAttributeMaxDynamicSharedMemorySize, GEMM_SMEM_B);

    copy_kernel<<<TOK, 256>>>((const float4*)x, (float4*)h, TOK * DIMM / 4);

    for (int l = 0; l < DEPTH; l++) {
        // --- attention block ---
        wconv<<<dim3(3 * DIMM / 32, DIMM / 32), dim3(32, 32)>>>(
            Wqkv + (size_t)l * DIMM * 3 * DIMM, DIMM, 3 * DIMM, w);
        ln_kernel<<<TOK, 256>>>(h, ln1g + (size_t)l * DIMM, ln1b + (size_t)l * DIMM, ah, al);
        gemm_mma<3><<<dim3(3 * DIMM / 128, TOK / 128), 256, GEMM_SMEM_B>>>(
            ah, al, w, (const float*)0, (float*)0, (__half*)0, (__half*)0,
            qb, kb, vb, TOK, 3 * DIMM, DIMM);
        attn_mma<<<dim3(SEQ / 128, HEADS, 2), 256, AT_SMEM>>>(qb, kb, vb, ah, al);
        wconv<<<dim3(DIMM / 32, DIMM / 32), dim3(32, 32)>>>(
            Wout + (size_t)l * DIMM * DIMM, DIMM, DIMM, w);
        gemm_mma<2><<<dim3(DIMM / 128, TOK / 128), 256, GEMM_SMEM_B>>>(
            ah, al, w, bout + (size_t)l * DIMM, h, (__half*)0, (__half*)0,
            (__half*)0, (__half*)0, (__half*)0, TOK, DIMM, DIMM);
        // --- ffn block ---
        ln_kernel<<<TOK, 256>>>(h, ln2g + (size_t)l * DIMM, ln2b + (size_t)l * DIMM, ah, al);
        wconv<<<dim3(MLPD / 32, DIMM / 32), dim3(32, 32)>>>(
            W1 + (size_t)l * DIMM * MLPD, DIMM, MLPD, w);
        gemm_mma<1><<<dim3(MLPD / 128, TOK / 128), 256, GEMM_SMEM_B>>>(
            ah, al, w, b1 + (size_t)l * MLPD, (float*)0, mh, ml,
            (__half*)0, (__half*)0, (__half*)0, TOK, MLPD, DIMM);
        wconv<<<dim3(DIMM / 32, MLPD / 32), dim3(32, 32)>>>(
            W2 + (size_t)l * MLPD * DIMM, MLPD, DIMM, w);
        gemm_mma<2><<<dim3(DIMM / 128, TOK / 128), 256, GEMM_SMEM_B>>>(
            mh, ml, w, b2 + (size_t)l * DIMM, h, (__half*)0, (__half*)0,
            (__half*)0, (__half*)0, (__half*)0, TOK, DIMM, MLPD);
    }
}

// round 7
// speedup vs baseline: 6.2983x; 1.7519x over previous
#include <cuda_runtime.h>
#include <cuda_fp16.h>
#include <math.h>
#include <stdint.h>

#define TOK   4096
#define SEQ   2048
#define DIMM  1024
#define HEADS 16
#define HD    64
#define MLPD  4096
#define DEPTH 6
#define ATT_SCALE 0.03125f

// ---------------- scratch ----------------
__device__ __half g_a[TOK * DIMM];        // ln out / attn out (single fp16)
__device__ __half g_m[TOK * MLPD];        // mlp hidden
__device__ __half g_w[DIMM * MLPD];       // transposed weight
__device__ __half g_q[TOK * DIMM];        // Q [token][dim]
__device__ __half g_k[TOK * DIMM];        // K [token][dim]
__device__ __half g_v[DIMM * TOK];        // V transposed [dim][token]

// ---------------- PTX helpers ----------------
__device__ __forceinline__ uint32_t smem_u32(const void* p) {
    uint32_t a;
    asm("{ .reg .u64 t; cvta.to.shared.u64 t, %1; cvt.u32.u64 %0, t; }" : "=r"(a) : "l"(p));
    return a;
}
#define SWZ(o) ((o) ^ (((o) >> 3) & 0x70))
__device__ __forceinline__ void cp16(uint32_t dst, const void* src) {
    asm volatile("cp.async.cg.shared.global [%0], [%1], 16;" :: "r"(dst), "l"(src));
}
#define CP_COMMIT()  asm volatile("cp.async.commit_group;")
#define CP_WAIT(n)   asm volatile("cp.async.wait_group " #n ";")

__device__ __forceinline__ void ldsm4(uint32_t* r, uint32_t addr) {
    asm volatile("ldmatrix.sync.aligned.m8n8.x4.shared.b16 {%0,%1,%2,%3}, [%4];"
        : "=r"(r[0]), "=r"(r[1]), "=r"(r[2]), "=r"(r[3]) : "r"(addr));
}
__device__ __forceinline__ void mma16816(float* c, const uint32_t* a, uint32_t b0, uint32_t b1) {
    asm volatile(
        "mma.sync.aligned.m16n8k16.row.col.f32.f16.f16.f32 "
        "{%0,%1,%2,%3}, {%4,%5,%6,%7}, {%8,%9}, {%0,%1,%2,%3};"
        : "+f"(c[0]), "+f"(c[1]), "+f"(c[2]), "+f"(c[3])
        : "r"(a[0]), "r"(a[1]), "r"(a[2]), "r"(a[3]), "r"(b0), "r"(b1));
}
__device__ __forceinline__ uint32_t packh(float a, float b) {
    __half2 t = __floats2half2_rn(a, b);
    return *(uint32_t*)&t;
}

// ---------------- copy ----------------
__global__ void copy_kernel(const float4* __restrict__ src, float4* __restrict__ dst, int n) {
    int i = blockIdx.x * blockDim.x + threadIdx.x;
    if (i < n) dst[i] = src[i];
}

// ---------------- weight convert + transpose: W[K,N] fp32 -> Wt[N,K] fp16 ----------------
__global__ __launch_bounds__(1024) void wconv(const float* __restrict__ W, int K, int N,
                                              __half* __restrict__ T) {
    __shared__ float t[32][33];
    int tx = threadIdx.x, ty = threadIdx.y;
    int n0 = blockIdx.x * 32, k0 = blockIdx.y * 32;
    t[ty][tx] = W[(size_t)(k0 + ty) * N + n0 + tx];
    __syncthreads();
    T[(size_t)(n0 + ty) * K + k0 + tx] = __float2half(t[tx][ty]);
}

// ---------------- layernorm -> fp16 ----------------
__global__ __launch_bounds__(256) void ln_kernel(const float* __restrict__ x,
                                                 const float* __restrict__ g,
                                                 const float* __restrict__ b,
                                                 __half* __restrict__ y) {
    int t = blockIdx.x, tid = threadIdx.x;
    const float4* xv = (const float4*)(x + (size_t)t * DIMM);
    float4 v = xv[tid];
    float s  = v.x + v.y + v.z + v.w;
    float s2 = v.x * v.x + v.y * v.y + v.z * v.z + v.w * v.w;
    #pragma unroll
    for (int o = 16; o > 0; o >>= 1) {
        s  += __shfl_xor_sync(0xffffffffu, s,  o);
        s2 += __shfl_xor_sync(0xffffffffu, s2, o);
    }
    __shared__ float rs[8], rs2[8];
    int w = tid >> 5, lane = tid & 31;
    if (lane == 0) { rs[w] = s; rs2[w] = s2; }
    __syncthreads();
    if (tid == 0) {
        float a = 0.f, a2 = 0.f;
        #pragma unroll
        for (int i = 0; i < 8; i++) { a += rs[i]; a2 += rs2[i]; }
        rs[0] = a; rs2[0] = a2;
    }
    __syncthreads();
    float mean = rs[0] * (1.f / DIMM);
    float var  = rs2[0] * (1.f / DIMM) - mean * mean;
    float inv  = rsqrtf(var + 1e-5f);
    float4 gv = ((const float4*)g)[tid];
    float4 bv = ((const float4*)b)[tid];
    float o0 = (v.x - mean) * inv * gv.x + bv.x;
    float o1 = (v.y - mean) * inv * gv.y + bv.y;
    float o2 = (v.z - mean) * inv * gv.z + bv.z;
    float o3 = (v.w - mean) * inv * gv.w + bv.w;
    *(uint2*)(y + (size_t)t * DIMM + tid * 4) = make_uint2(packh(o0, o1), packh(o2, o3));
}

// ---------------- HMMA GEMM, single fp16, BK=64, SW128 swizzle, 3-stage ----------------
// C[M,N] = A @ B^T (B stored [N,K]); fp32 accum.
// 128x128 CTA tile; 8 warps 2Mx4N, warp 64x32.
// EPI: 1 bias+gelu->fp16; 2 C += AB+bias; 3 qkv split write
#define TILEB 16384                       // 128 rows x 128 bytes
#define GSTG  (2 * TILEB)                 // 32768 per stage
#define GEMM_SMEM_B (3 * GSTG)            // 98304

template<int EPI>
__global__ __launch_bounds__(256, 2) void gemm_mma(
    const __half* __restrict__ A, const __half* __restrict__ B,
    const float* __restrict__ bias, float* __restrict__ C,
    __half* __restrict__ Oh,
    __half* __restrict__ Qb, __half* __restrict__ Kb, __half* __restrict__ Vb,
    int M, int N, int K)
{
    extern __shared__ __align__(1024) char smg[];
    const uint32_t sb = smem_u32(smg);
    const int tid = threadIdx.x;
    const int wid = tid >> 5, lane = tid & 31;
    const int wm = wid >> 2, wn = wid & 3;
    const int bn = blockIdx.x, bm = blockIdx.y;

    const __half* Ag = A + (size_t)bm * 128 * K;
    const __half* Bg = B + (size_t)bn * 128 * K;

    const int NC = K / 64;

    float acc[4][4][4];
    #pragma unroll
    for (int i = 0; i < 4; i++)
        #pragma unroll
        for (int j = 0; j < 4; j++)
            #pragma unroll
            for (int c = 0; c < 4; c++) acc[i][j][c] = 0.f;

    auto load_chunk = [&](int kc, int st) {
        uint32_t u = sb + st * GSTG;
        #pragma unroll
        for (int i = 0; i < 4; i++) {
            int f = tid + 256 * i;
            int r = f >> 3, c = f & 7;
            uint32_t sw = SWZ(r * 128 + c * 16);
            cp16(u + sw,         Ag + (size_t)r * K + kc * 64 + c * 8);
            cp16(u + TILEB + sw, Bg + (size_t)r * K + kc * 64 + c * 8);
        }
        CP_COMMIT();
    };

    load_chunk(0, 0);
    load_chunk(1, 1);

    for (int k = 0; k < NC; k++) {
        int st = k % 3;
        if (k == NC - 1) { CP_WAIT(0); } else { CP_WAIT(1); }
        __syncthreads();
        if (k + 2 < NC) load_chunk(k + 2, (k + 2) % 3);

        uint32_t u = sb + st * GSTG;
        #pragma unroll
        for (int ks = 0; ks < 4; ks++) {
            int cb = ks * 32 + (lane >> 4) * 16;
            uint32_t b_[4][2];
            #pragma unroll
            for (int bt = 0; bt < 2; bt++) {
                uint32_t t[4];
                ldsm4(t, u + TILEB + SWZ((wn * 32 + bt * 16 + (lane & 15)) * 128 + cb));
                b_[bt * 2 + 0][0] = t[0]; b_[bt * 2 + 0][1] = t[2];
                b_[bt * 2 + 1][0] = t[1]; b_[bt * 2 + 1][1] = t[3];
            }
            uint32_t a_[4][4];
            #pragma unroll
            for (int mt = 0; mt < 4; mt++)
                ldsm4(a_[mt], u + SWZ((wm * 64 + mt * 16 + (lane & 15)) * 128 + cb));
            #pragma unroll
            for (int mt = 0; mt < 4; mt++)
                #pragma unroll
                for (int nt = 0; nt < 4; nt++)
                    mma16816(acc[mt][nt], a_[mt], b_[nt][0], b_[nt][1]);
        }
    }

    // ---- epilogue ----
    const int rgrp = lane >> 2;
    const int cgrp = (lane & 3) * 2;
    const float* bp = (EPI == 1 || EPI == 2) ? (bias + (size_t)bn * 128) : (const float*)0;
    #pragma unroll
    for (int mt = 0; mt < 4; mt++) {
        #pragma unroll
        for (int half = 0; half < 2; half++) {
            size_t grow = (size_t)bm * 128 + wm * 64 + mt * 16 + rgrp + half * 8;
            #pragma unroll
            for (int nt = 0; nt < 4; nt++) {
                int lcol = wn * 32 + nt * 8 + cgrp;
                size_t gcol = (size_t)bn * 128 + lcol;
                float v0 = acc[mt][nt][half * 2 + 0];
                float v1 = acc[mt][nt][half * 2 + 1];
                if (EPI == 1) {
                    float t0 = v0 + bp[lcol], t1 = v1 + bp[lcol + 1];
                    float g0 = 0.5f * t0 * (1.f + erff(t0 * 0.70710678118654752f));
                    float g1 = 0.5f * t1 * (1.f + erff(t1 * 0.70710678118654752f));
                    *(uint32_t*)(Oh + grow * N + gcol) = packh(g0, g1);
                } else if (EPI == 2) {
                    float2 old = *(float2*)(C + grow * N + gcol);
                    *(float2*)(C + grow * N + gcol) =
                        make_float2(old.x + v0 + bp[lcol], old.y + v1 + bp[lcol + 1]);
                } else {   // EPI == 3: qkv split
                    if (gcol < DIMM) {
                        *(uint32_t*)(Qb + grow * DIMM + gcol) = packh(v0, v1);
                    } else if (gcol < 2 * DIMM) {
                        *(uint32_t*)(Kb + grow * DIMM + gcol - DIMM) = packh(v0, v1);
                    } else {
                        size_t d = gcol - 2 * DIMM;
                        Vb[d * TOK + grow]       = __float2half(v0);
                        Vb[(d + 1) * TOK + grow] = __float2half(v1);
                    }
                }
            }
        }
    }
}

// ---------------- HMMA flash attention: all single fp16, fp32 softmax ----------------
// block: 128 q-rows x 1 head; 8 warps x m16. KV tiles of 64; 3 stages x {K 8KB, V 8KB}.
#define AT_SMEM 49152

__global__ __launch_bounds__(256) void attn_mma(
    const __half* __restrict__ qb,
    const __half* __restrict__ kb, const __half* __restrict__ vb,
    __half* __restrict__ oh)
{
    extern __shared__ __align__(1024) char sm[];
    const uint32_t base = smem_u32(sm);
    const int tid = threadIdx.x, wid = tid >> 5, lane = tid & 31;
    const int qb_ = blockIdx.x, head = blockIdx.y, batch = blockIdx.z;
    const size_t tok0 = (size_t)batch * SEQ;

    // ---- stage Q, extract fragments ----
    {
        const __half* qg = qb + (tok0 + qb_ * 128) * DIMM + head * HD;
        #pragma unroll
        for (int i = 0; i < 4; i++) {
            int f = tid + 256 * i;
            int r = f >> 3, c = f & 7;
            cp16(base + SWZ(r * 128 + c * 16), qg + (size_t)r * DIMM + c * 8);
        }
        CP_COMMIT(); CP_WAIT(0);
    }
    __syncthreads();
    uint32_t qf[4][4];
    {
        int rb = (wid * 16 + (lane & 15)) * 128 + (lane >> 4) * 16;
        #pragma unroll
        for (int kt = 0; kt < 4; kt++)
            ldsm4(qf[kt], base + SWZ(rb + kt * 32));
    }
    __syncthreads();

    auto loadkv = [&](int it, int st) {
        uint32_t u = base + st * 16384;
        const __half* kg = kb + (tok0 + it * 64) * DIMM + head * HD;
        const __half* vg = vb + (size_t)(head * HD) * TOK + tok0 + it * 64;
        #pragma unroll
        for (int i = 0; i < 2; i++) {
            int f = tid + 256 * i;
            int r = f >> 3, c = f & 7;
            uint32_t sw = SWZ(r * 128 + c * 16);
            cp16(u + sw,        kg + (size_t)r * DIMM + c * 8);
            cp16(u + 8192 + sw, vg + (size_t)r * TOK + c * 8);
        }
        CP_COMMIT();
    };

    float m0 = -INFINITY, m1 = -INFINITY, l0 = 0.f, l1 = 0.f;
    float O[8][4];
    #pragma unroll
    for (int i = 0; i < 8; i++)
        #pragma unroll
        for (int j = 0; j < 4; j++) O[i][j] = 0.f;

    loadkv(0, 0);
    loadkv(1, 1);

    const int NT = SEQ / 64;
    for (int it = 0; it < NT; it++) {
        int st = it % 3;
        if (it == NT - 1) { CP_WAIT(0); } else { CP_WAIT(1); }
        __syncthreads();
        if (it + 2 < NT) loadkv(it + 2, (it + 2) % 3);
        uint32_t u = base + st * 16384;

        // ---- S = scale * Q K^T ----
        float S[8][4];
        #pragma unroll
        for (int i = 0; i < 8; i++)
            #pragma unroll
            for (int j = 0; j < 4; j++) S[i][j] = 0.f;

        #pragma unroll
        for (int kt = 0; kt < 4; kt++) {
            uint32_t th[4][4];
            #pragma unroll
            for (int g = 0; g < 4; g++)
                ldsm4(th[g], u + SWZ((g * 16 + (lane & 15)) * 128 + kt * 32 + (lane >> 4) * 16));
            #pragma unroll
            for (int g = 0; g < 4; g++) {
                mma16816(S[2 * g],     qf[kt], th[g][0], th[g][2]);
                mma16816(S[2 * g + 1], qf[kt], th[g][1], th[g][3]);
            }
        }

        // ---- fp32 online softmax ----
        #pragma unroll
        for (int i = 0; i < 8; i++)
            #pragma unroll
            for (int j = 0; j < 4; j++) S[i][j] *= ATT_SCALE;

        float mx0 = S[0][0], mx1 = S[0][2];
        #pragma unroll
        for (int i = 0; i < 8; i++) {
            mx0 = fmaxf(mx0, fmaxf(S[i][0], S[i][1]));
            mx1 = fmaxf(mx1, fmaxf(S[i][2], S[i][3]));
        }
        mx0 = fmaxf(mx0, __shfl_xor_sync(0xffffffffu, mx0, 1));
        mx0 = fmaxf(mx0, __shfl_xor_sync(0xffffffffu, mx0, 2));
        mx1 = fmaxf(mx1, __shfl_xor_sync(0xffffffffu, mx1, 1));
        mx1 = fmaxf(mx1, __shfl_xor_sync(0xffffffffu, mx1, 2));
        float mn0 = fmaxf(m0, mx0), mn1 = fmaxf(m1, mx1);
        float c0 = __expf(m0 - mn0), c1 = __expf(m1 - mn1);
        m0 = mn0; m1 = mn1;
        float s0 = 0.f, s1 = 0.f;
        #pragma unroll
        for (int i = 0; i < 8; i++) {
            S[i][0] = __expf(S[i][0] - mn0); S[i][1] = __expf(S[i][1] - mn0);
            S[i][2] = __expf(S[i][2] - mn1); S[i][3] = __expf(S[i][3] - mn1);
            s0 += S[i][0] + S[i][1];
            s1 += S[i][2] + S[i][3];
        }
        s0 += __shfl_xor_sync(0xffffffffu, s0, 1);
        s0 += __shfl_xor_sync(0xffffffffu, s0, 2);
        s1 += __shfl_xor_sync(0xffffffffu, s1, 1);
        s1 += __shfl_xor_sync(0xffffffffu, s1, 2);
        l0 = l0 * c0 + s0;
        l1 = l1 * c1 + s1;
        #pragma unroll
        for (int i = 0; i < 8; i++) {
            O[i][0] *= c0; O[i][1] *= c0;
            O[i][2] *= c1; O[i][3] *= c1;
        }

        // ---- O += P V ----
        #pragma unroll
        for (int kt = 0; kt < 4; kt++) {
            uint32_t p_[4];
            p_[0] = packh(S[2 * kt][0], S[2 * kt][1]);
            p_[1] = packh(S[2 * kt][2], S[2 * kt][3]);
            p_[2] = packh(S[2 * kt + 1][0], S[2 * kt + 1][1]);
            p_[3] = packh(S[2 * kt + 1][2], S[2 * kt + 1][3]);
            uint32_t tv[4][4];
            #pragma unroll
            for (int g = 0; g < 4; g++)
                ldsm4(tv[g], u + 8192 + SWZ((g * 16 + (lane & 15)) * 128 + kt * 32 + (lane >> 4) * 16));
            #pragma unroll
            for (int g = 0; g < 4; g++) {
                mma16816(O[2 * g],     p_, tv[g][0], tv[g][2]);
                mma16816(O[2 * g + 1], p_, tv[g][1], tv[g][3]);
            }
        }
    }

    // ---- normalize + write ----
    float i0 = 1.f / l0, i1 = 1.f / l1;
    size_t row0 = tok0 + (size_t)qb_ * 128 + wid * 16 + (lane >> 2);
    int colb = head * HD + (lane & 3) * 2;
    #pragma unroll
    for (int nt = 0; nt < 8; nt++) {
        size_t idx0 = row0 * DIMM + colb + nt * 8;
        size_t idx1 = (row0 + 8) * DIMM + colb + nt * 8;
        *(uint32_t*)(oh + idx0) = packh(O[nt][0] * i0, O[nt][1] * i0);
        *(uint32_t*)(oh + idx1) = packh(O[nt][2] * i1, O[nt][3] * i1);
    }
}

// ---------------- driver ----------------
extern "C" void kernel_launch(void* const* d_in, const int* in_sizes, int n_in,
                              void* d_out, int out_size)
{
    const float* x    = (const float*)d_in[0];
    const float* Wqkv = (const float*)d_in[1];
    const float* Wout = (const float*)d_in[2];
    const float* bout = (const float*)d_in[3];
    const float* ln1g = (const float*)d_in[4];
    const float* ln1b = (const float*)d_in[5];
    const float* ln2g = (const float*)d_in[6];
    const float* ln2b = (const float*)d_in[7];
    const float* W1   = (const float*)d_in[8];
    const float* b1   = (const float*)d_in[9];
    const float* W2   = (const float*)d_in[10];
    const float* b2   = (const float*)d_in[11];
    float* h = (float*)d_out;

    __half *a, *m, *w, *qb, *kb, *vb;
    cudaGetSymbolAddress((void**)&a, g_a);
    cudaGetSymbolAddress((void**)&m, g_m);
    cudaGetSymbolAddress((void**)&w, g_w);
    cudaGetSymbolAddress((void**)&qb, g_q);
    cudaGetSymbolAddress((void**)&kb, g_k);
    cudaGetSymbolAddress((void**)&vb, g_v);

    cudaFuncSetAttribute(attn_mma,    cudaFuncAttributeMaxDynamicSharedMemorySize, AT_SMEM);
    cudaFuncSetAttribute(gemm_mma<1>, cudaFuncAttributeMaxDynamicSharedMemorySize, GEMM_SMEM_B);
    cudaFuncSetAttribute(gemm_mma<2>, cudaFuncAttributeMaxDynamicSharedMemorySize, GEMM_SMEM_B);
    cudaFuncSetAttribute(gemm_mma<3>, cudaFuncAttributeMaxDynamicSharedMemorySize, GEMM_SMEM_B);

    copy_kernel<<<TOK, 256>>>((const float4*)x, (float4*)h, TOK * DIMM / 4);

    for (int l = 0; l < DEPTH; l++) {
        // --- attention block ---
        wconv<<<dim3(3 * DIMM / 32, DIMM / 32), dim3(32, 32)>>>(
            Wqkv + (size_t)l * DIMM * 3 * DIMM, DIMM, 3 * DIMM, w);
        ln_kernel<<<TOK, 256>>>(h, ln1g + (size_t)l * DIMM, ln1b + (size_t)l * DIMM, a);
        gemm_mma<3><<<dim3(3 * DIMM / 128, TOK / 128), 256, GEMM_SMEM_B>>>(
            a, w, (const float*)0, (float*)0, (__half*)0,
            qb, kb, vb, TOK, 3 * DIMM, DIMM);
        attn_mma<<<dim3(SEQ / 128, HEADS, 2), 256, AT_SMEM>>>(qb, kb, vb, a);
        wconv<<<dim3(DIMM / 32, DIMM / 32), dim3(32, 32)>>>(
            Wout + (size_t)l * DIMM * DIMM, DIMM, DIMM, w);
        gemm_mma<2><<<dim3(DIMM / 128, TOK / 128), 256, GEMM_SMEM_B>>>(
            a, w, bout + (size_t)l * DIMM, h, (__half*)0,
            (__half*)0, (__half*)0, (__half*)0, TOK, DIMM, DIMM);
        // --- ffn block ---
        ln_kernel<<<TOK, 256>>>(h, ln2g + (size_t)l * DIMM, ln2b + (size_t)l * DIMM, a);
        wconv<<<dim3(MLPD / 32, DIMM / 32), dim3(32, 32)>>>(
            W1 + (size_t)l * DIMM * MLPD, DIMM, MLPD, w);
        gemm_mma<1><<<dim3(MLPD / 128, TOK / 128), 256, GEMM_SMEM_B>>>(
            a, w, b1 + (size_t)l * MLPD, (float*)0, m,
            (__half*)0, (__half*)0, (__half*)0, TOK, MLPD, DIMM);
        wconv<<<dim3(DIMM / 32, MLPD / 32), dim3(32, 32)>>>(
            W2 + (size_t)l * MLPD * DIMM, MLPD, DIMM, w);
        gemm_mma<2><<<dim3(DIMM / 128, TOK / 128), 256, GEMM_SMEM_B>>>(
            m, w, b2 + (size_t)l * DIMM, h, (__half*)0,
            (__half*)0, (__half*)0, (__half*)0, TOK, DIMM, MLPD);
    }
}